// round 2
// baseline (speedup 1.0000x reference)
#include <cuda_runtime.h>
#include <math.h>

#define T_ENC  16384
#define HID    512
#define EMB    512
#define G3     1536        // 3*HID
#define VOCAB  31
#define STEPS  100
#define EOS    29
#define NB     128         // persistent blocks (<= 148 SMs, co-resident)
#define NT     256
#define NW     (NT/32)
#define CHUNK  (T_ENC/NB)  // 128 rows per block
#define SCALE  0.04419417382415922f   // 1/sqrt(512)

#define OUT_LEN (STEPS*VOCAB)     // 3100
#define OUT_ATT (STEPS*VOCAB+1)   // 3101

// -------- persistent device scratch (no allocations allowed) --------
__device__ float g_gx[VOCAB * G3];     // precomputed gx table per token
__device__ float g_gh[2][G3];          // gh double-buffered by step parity
__device__ float g_scores[T_ENC];      // raw masked scores of current step
__device__ float g_pm[NB];             // per-block local max
__device__ float g_ps[NB];             // per-block local sumexp
__device__ float g_z[NB][32];          // per-block w_out-projected partial summary
__device__ float g_mg, g_sg;           // global softmax stats of the step
__device__ int   g_token;
__device__ int   g_len;
__device__ int   g_bar_cnt = 0;
__device__ volatile int g_bar_gen = 0;

// -------- software grid barrier (gen/count; safe across launches) --------
__device__ __forceinline__ void gsync() {
    __syncthreads();
    if (threadIdx.x == 0) {
        __threadfence();
        int gen = g_bar_gen;
        if (atomicAdd(&g_bar_cnt, 1) == NB - 1) {
            atomicExch(&g_bar_cnt, 0);
            __threadfence();
            atomicExch((int*)&g_bar_gen, gen + 1);
        } else {
            while (g_bar_gen == gen) { __nanosleep(32); }
            __threadfence();
        }
    }
    __syncthreads();
}

__device__ __forceinline__ float wsum(float v) {
    #pragma unroll
    for (int o = 16; o; o >>= 1) v += __shfl_xor_sync(0xffffffffu, v, o);
    return v;
}
__device__ __forceinline__ float wmax(float v) {
    #pragma unroll
    for (int o = 16; o; o >>= 1) v = fmaxf(v, __shfl_xor_sync(0xffffffffu, v, o));
    return v;
}

__global__ void __launch_bounds__(NT, 1)
decoder_kernel(const float* __restrict__ enc,    // [T_ENC, 1024] = [keys|values]
               const float* __restrict__ embed,  // [31, 512]
               const float* __restrict__ w_ih,   // [1536, 512]
               const float* __restrict__ w_hh,   // [1536, 512]
               const float* __restrict__ b_ih,   // [1536]
               const float* __restrict__ b_hh,   // [1536]
               const float* __restrict__ w_out,  // [31, 1024]
               const float* __restrict__ b_out,  // [31]
               float* __restrict__ out)
{
    __shared__ float sh_h[HID];     // h_new (redundant full copy per block)
    __shared__ float sc[CHUNK];     // scores -> exp(scores - m_b)
    __shared__ float s_u[HID];      // partial summary u_b
    __shared__ float s_red[NW];
    __shared__ float s_bc[2];
    __shared__ float s_c[NB];       // block 0: combine coefficients
    __shared__ float s_lg[32];      // block 0: logits

    const int tid  = threadIdx.x;
    const int b    = blockIdx.x;
    const int lane = tid & 31;
    const int warp = tid >> 5;
    const int j0   = b * CHUNK;

    // =============== setup phase ===============
    if (b == 0) {
        for (int i = tid; i < G3; i += NT) __stcg(&g_gh[0][i], b_hh[i]);  // h0=0 -> gh0=b_hh
        if (tid == 0) { __stcg(&g_token, EOS); g_len = STEPS; }
    }
    // gx table: gx[v][r] = dot(embed[v], w_ih[r]) + b_ih[r]; warp-per-row, w_ih row in regs
    {
        int wg = b * NW + warp;
        for (int r = wg; r < G3; r += NB * NW) {
            const float* wr = w_ih + (size_t)r * EMB;
            float wreg[16];
            #pragma unroll
            for (int i = 0; i < 16; i++) wreg[i] = wr[lane + 32 * i];
            float bias = b_ih[r];
            for (int v = 0; v < VOCAB; v++) {
                const float* er = embed + (size_t)v * EMB;
                float acc = 0.f;
                #pragma unroll
                for (int i = 0; i < 16; i++) acc += wreg[i] * er[lane + 32 * i];
                acc = wsum(acc);
                if (lane == 0) g_gx[v * G3 + r] = acc + bias;
            }
        }
    }
    gsync();

    // h_prev lives in registers: thread owns dims (tid) and (tid+NT)
    float hreg0 = 0.f, hreg1 = 0.f;

    for (int t = 0; t <= STEPS; t++) {
        const int p = t & 1, q = p ^ 1;

        // ---- write attention output of step t-1 (global m,s now known) ----
        if (t > 0) {
            float mg  = __ldcg(&g_mg);
            float inv = 1.f / __ldcg(&g_sg);
            for (int r = tid; r < CHUNK; r += NT)
                out[OUT_ATT + (size_t)(t - 1) * T_ENC + j0 + r] =
                    expf(g_scores[j0 + r] - mg) * inv;
        }
        if (t == STEPS) break;

        // ---- GRU gate combine (redundant per block; gh precomputed last step) ----
        {
            int tok = __ldcg(&g_token);
            const float* gx = g_gx + (size_t)tok * G3;
            {
                int i = tid;
                float ghr = __ldcg(&g_gh[p][i]);
                float ghz = __ldcg(&g_gh[p][HID + i]);
                float ghn = __ldcg(&g_gh[p][2 * HID + i]);
                float r_ = 1.f / (1.f + expf(-(gx[i] + ghr)));
                float z_ = 1.f / (1.f + expf(-(gx[HID + i] + ghz)));
                float n_ = tanhf(gx[2 * HID + i] + r_ * ghn);
                hreg0 = (1.f - z_) * n_ + z_ * hreg0;
                sh_h[i] = hreg0;
            }
            {
                int i = tid + NT;
                float ghr = __ldcg(&g_gh[p][i]);
                float ghz = __ldcg(&g_gh[p][HID + i]);
                float ghn = __ldcg(&g_gh[p][2 * HID + i]);
                float r_ = 1.f / (1.f + expf(-(gx[i] + ghr)));
                float z_ = 1.f / (1.f + expf(-(gx[HID + i] + ghz)));
                float n_ = tanhf(gx[2 * HID + i] + r_ * ghn);
                hreg1 = (1.f - z_) * n_ + z_ * hreg1;
                sh_h[i] = hreg1;
            }
        }
        __syncthreads();

        // ---- gh(t+1) = h_new @ w_hh^T + b_hh : 12 rows per block ----
        for (int k = warp; k < 12; k += NW) {
            int o = b * 12 + k;
            const float* wr = w_hh + (size_t)o * HID;
            float acc = 0.f;
            for (int d = lane; d < HID; d += 32) acc += sh_h[d] * wr[d];
            acc = wsum(acc);
            if (lane == 0) __stcg(&g_gh[q][o], acc + b_hh[o]);
        }

        // ---- scores for chunk: s_j = scale * dot(h_new, key_j), masked ----
        for (int r = warp; r < CHUNK; r += NW) {
            int j = j0 + r;
            const float4* k4 = (const float4*)(enc + (size_t)j * 1024);
            float acc = 0.f;
            bool anyne = false;
            #pragma unroll 4
            for (int c = lane; c < 128; c += 32) {
                float4 v = k4[c];
                anyne |= (v.x != 30.f) | (v.y != 30.f) | (v.z != 30.f) | (v.w != 30.f);
                int d = c * 4;
                acc += v.x * sh_h[d] + v.y * sh_h[d + 1] + v.z * sh_h[d + 2] + v.w * sh_h[d + 3];
            }
            acc = wsum(acc);
            bool msk = __any_sync(0xffffffffu, anyne);
            if (lane == 0) {
                float s = msk ? acc * SCALE : -1.0e9f;
                sc[r] = s;
                g_scores[j] = s;
            }
        }
        __syncthreads();

        // ---- local softmax stats over the chunk ----
        float lm = -3.4e38f;
        for (int r = tid; r < CHUNK; r += NT) lm = fmaxf(lm, sc[r]);
        lm = wmax(lm);
        if (lane == 0) s_red[warp] = lm;
        __syncthreads();
        if (warp == 0) {
            float v = (lane < NW) ? s_red[lane] : -3.4e38f;
            v = wmax(v);
            if (lane == 0) s_bc[0] = v;
        }
        __syncthreads();
        float mb = s_bc[0];
        float ls = 0.f;
        for (int r = tid; r < CHUNK; r += NT) {
            float e = expf(sc[r] - mb);
            sc[r] = e;
            ls += e;
        }
        ls = wsum(ls);
        if (lane == 0) s_red[warp] = ls;
        __syncthreads();
        if (warp == 0) {
            float v = (lane < NW) ? s_red[lane] : 0.f;
            v = wsum(v);
            if (lane == 0) s_bc[1] = v;
        }
        __syncthreads();
        if (tid == 0) { __stcg(&g_pm[b], mb); __stcg(&g_ps[b], s_bc[1]); }

        // ---- u_b = sum_j e_j * v_j  (rows split between thread halves) ----
        {
            int half  = tid >> 7;
            int dbase = tid & 127;                 // float4 index into 512 dims
            float4 u4 = make_float4(0.f, 0.f, 0.f, 0.f);
            int r0 = half * (CHUNK / 2);
            #pragma unroll 4
            for (int r = 0; r < CHUNK / 2; ++r) {
                float e = sc[r0 + r];
                const float4* vr = (const float4*)(enc + (size_t)(j0 + r0 + r) * 1024 + 512);
                float4 v = vr[dbase];
                u4.x += e * v.x; u4.y += e * v.y; u4.z += e * v.z; u4.w += e * v.w;
            }
            float4* up = (float4*)s_u;
            if (half) up[dbase] = u4;
            __syncthreads();
            if (!half) {
                float4 o = up[dbase];
                o.x += u4.x; o.y += u4.y; o.z += u4.z; o.w += u4.w;
                up[dbase] = o;
            }
            __syncthreads();
        }

        // ---- z_b[k] = w_out[k, :512] . u_b  (31 tiny dots) ----
        for (int k = warp; k < VOCAB; k += NW) {
            const float* wr = w_out + (size_t)k * 1024;
            float acc = 0.f;
            for (int d = lane; d < HID; d += 32) acc += s_u[d] * wr[d];
            acc = wsum(acc);
            if (lane == 0) __stcg(&g_z[b][k], acc);
        }
        gsync();

        // =============== serial combine phase (block 0) ===============
        if (b == 0) {
            float gm = -3.4e38f;
            for (int i = tid; i < NB; i += NT) gm = fmaxf(gm, __ldcg(&g_pm[i]));
            gm = wmax(gm);
            if (lane == 0) s_red[warp] = gm;
            __syncthreads();
            if (warp == 0) {
                float v = (lane < NW) ? s_red[lane] : -3.4e38f;
                v = wmax(v);
                if (lane == 0) s_bc[0] = v;
            }
            __syncthreads();
            float mg = s_bc[0];
            float sp = 0.f;
            for (int i = tid; i < NB; i += NT) {
                float c = expf(__ldcg(&g_pm[i]) - mg);
                s_c[i] = c;
                sp += c * __ldcg(&g_ps[i]);
            }
            sp = wsum(sp);
            if (lane == 0) s_red[warp] = sp;
            __syncthreads();
            if (warp == 0) {
                float v = (lane < NW) ? s_red[lane] : 0.f;
                v = wsum(v);
                if (lane == 0) s_bc[1] = v;
            }
            __syncthreads();
            float sg = s_bc[1];
            float inv = 1.f / sg;

            for (int k = warp; k < VOCAB; k += NW) {
                float a1 = 0.f;
                for (int i = lane; i < NB; i += 32) a1 += s_c[i] * __ldcg(&g_z[i][k]);
                float a2 = 0.f;
                const float* wr = w_out + (size_t)k * 1024;
                for (int d = lane; d < HID; d += 32) a2 += wr[512 + d] * sh_h[d];
                a1 = wsum(a1);
                a2 = wsum(a2);
                if (lane == 0) s_lg[k] = a1 * inv + a2 + b_out[k];
            }
            __syncthreads();
            for (int k = tid; k < VOCAB; k += NT) out[(size_t)t * VOCAB + k] = s_lg[k];
            if (tid == 0) {
                int best = 0; float bv = s_lg[0];
                #pragma unroll
                for (int k = 1; k < VOCAB; k++)
                    if (s_lg[k] > bv) { bv = s_lg[k]; best = k; }
                __stcg(&g_token, best);
                __stcg(&g_mg, mg);
                __stcg(&g_sg, sg);
                if (best == EOS && g_len == STEPS) g_len = t;
                if (t == STEPS - 1) out[OUT_LEN] = (float)g_len;
            }
        }
        gsync();
    }
}

extern "C" void kernel_launch(void* const* d_in, const int* in_sizes, int n_in,
                              void* d_out, int out_size) {
    const float* enc    = (const float*)d_in[0];  // encoding (1,16384,1024)
    // d_in[1] = encoding_lens (int64) — unused (mask is PAD-value based)
    const float* embed  = (const float*)d_in[2];
    const float* w_ih   = (const float*)d_in[3];
    const float* w_hh   = (const float*)d_in[4];
    const float* b_ih   = (const float*)d_in[5];
    const float* b_hh   = (const float*)d_in[6];
    const float* w_out  = (const float*)d_in[7];
    const float* b_out  = (const float*)d_in[8];
    float* out = (float*)d_out;

    decoder_kernel<<<NB, NT>>>(enc, embed, w_ih, w_hh, b_ih, b_hh,
                               w_out, b_out, out);
}

// round 3
// speedup vs baseline: 1.6468x; 1.6468x over previous
#include <cuda_runtime.h>
#include <cuda_fp16.h>
#include <math.h>

#define T_ENC  16384
#define HID    512
#define EMB    512
#define G3     1536
#define VOCAB  31
#define STEPS  100
#define EOS    29
#define NB     128
#define NT     512
#define NW     (NT/32)          // 16 warps
#define CHUNK  (T_ENC/NB)       // 128 rows/block
#define SCALE  0.04419417382415922f

#define OUT_LEN (STEPS*VOCAB)
#define OUT_ATT (STEPS*VOCAB+1)

// ---------------- persistent device scratch ----------------
__device__ int4  g_vals[T_ENC * 64];       // fp16 values, 64 int4 (=512 half) per row
__device__ float g_gx[VOCAB * G3];
__device__ float g_gh[2][G3];
__device__ float g_pm[NB];
__device__ float g_ps[NB];
__device__ float g_z[NB][32];
__device__ float g_mg, g_sg;
__device__ int   g_token;
__device__ int   g_len;
__device__ int   g_cnt[2] = {0, 0};        // arrive counters (parity slots, self-reset)
__device__ volatile int g_done = 0;        // epoch broadcast flag (reset at kernel end)
__device__ int   g_bar_cnt = 0;            // legacy full barrier (end-of-kernel only)
__device__ volatile int g_bar_gen = 0;

// ---------------- dynamic smem layout ----------------
struct SM {
    uint2  keys[CHUNK][128];   // fp16 keys: 1KB/row = 131072 B
    float  wout[VOCAB][512];   // w_out[:, :512] cache: 63488 B
    float  part[8][512];       // summary partials: 16384 B
    float  h[512];
    float  u[512];
    float  sc[CHUNK];          // raw -> exp
    float  raw[CHUNK];         // raw masked scores (for attn output next step)
    float  maskb[CHUNK];       // 1 = valid, 0 = pad
    float  red[NW];
    float  bc[2];
    float  c[NB];              // block0: combine coefficients
    float  lg[32];             // block0: logits
};

__device__ __forceinline__ float wsum(float v) {
    #pragma unroll
    for (int o = 16; o; o >>= 1) v += __shfl_xor_sync(0xffffffffu, v, o);
    return v;
}
__device__ __forceinline__ float wmax(float v) {
    #pragma unroll
    for (int o = 16; o; o >>= 1) v = fmaxf(v, __shfl_xor_sync(0xffffffffu, v, o));
    return v;
}

// legacy full grid barrier (used once at kernel end, safe across replays)
__device__ __forceinline__ void gsync_full() {
    __syncthreads();
    if (threadIdx.x == 0) {
        __threadfence();
        int gen = g_bar_gen;
        if (atomicAdd(&g_bar_cnt, 1) == NB - 1) {
            atomicExch(&g_bar_cnt, 0);
            __threadfence();
            atomicExch((int*)&g_bar_gen, gen + 1);
        } else {
            while (g_bar_gen == gen) { __nanosleep(32); }
            __threadfence();
        }
    }
    __syncthreads();
}

__global__ void __launch_bounds__(NT, 1)
decoder_kernel(const float* __restrict__ enc,
               const float* __restrict__ embed,
               const float* __restrict__ w_ih,
               const float* __restrict__ w_hh,
               const float* __restrict__ b_ih,
               const float* __restrict__ b_hh,
               const float* __restrict__ w_out,
               const float* __restrict__ b_out,
               float* __restrict__ out)
{
    extern __shared__ __align__(16) unsigned char smem_raw[];
    SM* sm = (SM*)smem_raw;

    const int tid  = threadIdx.x;
    const int b    = blockIdx.x;
    const int lane = tid & 31;
    const int warp = tid >> 5;
    const int j0   = b * CHUNK;

    // w_hh rows cached in registers: warp k (<12) owns row b*12+k
    float whh[16];
    float bhh = 0.f;

    // ================= setup (epoch 0) =================
    if (b == 0) {
        for (int i = tid; i < G3; i += NT) g_gh[0][i] = b_hh[i];   // h0=0
        if (tid == 0) { g_token = EOS; g_len = STEPS; }
    }
    // convert keys -> smem fp16, values -> global fp16; compute mask
    for (int r = warp; r < CHUNK; r += NW) {
        int j = j0 + r;
        const float4* src = (const float4*)(enc + (size_t)j * 1024);
        bool anyne = false;
        #pragma unroll
        for (int c = lane; c < 128; c += 32) {
            float4 f = src[c];                          // keys
            anyne |= (f.x != 30.f) | (f.y != 30.f) | (f.z != 30.f) | (f.w != 30.f);
            uint2 pk;
            __half2 a = __floats2half2_rn(f.x, f.y);
            __half2 bb = __floats2half2_rn(f.z, f.w);
            pk.x = *(unsigned*)&a; pk.y = *(unsigned*)&bb;
            sm->keys[r][c] = pk;
            float4 v = src[128 + c];                    // values
            __half2 c0 = __floats2half2_rn(v.x, v.y);
            __half2 c1 = __floats2half2_rn(v.z, v.w);
            uint2 pv; pv.x = *(unsigned*)&c0; pv.y = *(unsigned*)&c1;
            ((uint2*)g_vals)[(size_t)j * 128 + c] = pv;
        }
        bool msk = __any_sync(0xffffffffu, anyne);
        if (lane == 0) sm->maskb[r] = msk ? 1.f : 0.f;
    }
    // w_out[:, :512] -> smem
    for (int idx = tid; idx < VOCAB * 512; idx += NT) {
        int k = idx >> 9, d = idx & 511;
        sm->wout[k][d] = w_out[(size_t)k * 1024 + d];
    }
    // w_hh rows -> regs
    if (warp < 12) {
        int o = b * 12 + warp;
        const float* wr = w_hh + (size_t)o * HID;
        #pragma unroll
        for (int i = 0; i < 16; i++) whh[i] = wr[lane + 32 * i];
        bhh = b_hh[o];
    }
    // gx table: gx[v][r] = embed[v] . w_ih[r] + b_ih[r]
    {
        int wg = b * NW + warp;
        for (int r = wg; r < G3; r += NB * NW) {
            const float* wr = w_ih + (size_t)r * EMB;
            float wreg[16];
            #pragma unroll
            for (int i = 0; i < 16; i++) wreg[i] = wr[lane + 32 * i];
            float bias = b_ih[r];
            for (int v = 0; v < VOCAB; v++) {
                const float* er = embed + (size_t)v * EMB;
                float acc = 0.f;
                #pragma unroll
                for (int i = 0; i < 16; i++) acc += wreg[i] * er[lane + 32 * i];
                acc = wsum(acc);
                if (lane == 0) g_gx[v * G3 + r] = acc + bias;
            }
        }
    }
    // ---- epoch 0 sync: arrive -> block0 -> done=1 ----
    __syncthreads();
    if (tid == 0) { __threadfence(); atomicAdd(&g_cnt[0], 1); }
    if (b == 0 && tid == 0) {
        while (*(volatile int*)&g_cnt[0] < NB) __nanosleep(32);
        atomicExch(&g_cnt[0], 0);
        __threadfence();
        atomicExch((int*)&g_done, 1);
    }
    if (tid == 0) {
        while (g_done < 1) __nanosleep(32);
        __threadfence();
    }
    __syncthreads();

    // ================= decode loop =================
    float hreg = 0.f;   // thread owns h[tid]

    for (int t = 0; t <= STEPS; t++) {
        const int p = t & 1, q = p ^ 1;

        // ---- attention output of step t-1 (global stats now known) ----
        if (t > 0 && tid < CHUNK) {
            float mg  = __ldcg(&g_mg);
            float inv = 1.f / __ldcg(&g_sg);
            out[OUT_ATT + (size_t)(t - 1) * T_ENC + j0 + tid] =
                __expf(sm->raw[tid] - mg) * inv;
        }
        if (t == STEPS) break;

        // ---- GRU combine (redundant per block), h[tid] per thread ----
        {
            int tok = __ldcg(&g_token);
            const float* gx = g_gx + (size_t)tok * G3;
            float ghr = __ldcg(&g_gh[p][tid]);
            float ghz = __ldcg(&g_gh[p][HID + tid]);
            float ghn = __ldcg(&g_gh[p][2 * HID + tid]);
            float r_ = 1.f / (1.f + expf(-(gx[tid] + ghr)));
            float z_ = 1.f / (1.f + expf(-(gx[HID + tid] + ghz)));
            float n_ = tanhf(gx[2 * HID + tid] + r_ * ghn);
            hreg = (1.f - z_) * n_ + z_ * hreg;
            sm->h[tid] = hreg;
        }
        __syncthreads();

        // ---- gh(t+1) = h_new @ w_hh^T + b_hh (regs), 12 rows/block ----
        if (warp < 12) {
            float acc = 0.f;
            #pragma unroll
            for (int i = 0; i < 16; i++) acc += whh[i] * sm->h[lane + 32 * i];
            acc = wsum(acc);
            if (lane == 0) __stcg(&g_gh[q][b * 12 + warp], acc + bhh);
        }

        // ---- scores: warp handles 8 rows, batches of 4 (smem keys) ----
        {
            int rbase = warp * 8;
            #pragma unroll
            for (int rb = 0; rb < 8; rb += 4) {
                float a0 = 0.f, a1 = 0.f, a2 = 0.f, a3 = 0.f;
                #pragma unroll
                for (int c = 0; c < 2; c++) {
                    int ci = lane + 32 * c;
                    float4 ha = *(const float4*)&sm->h[ci * 8];
                    float4 hb = *(const float4*)&sm->h[ci * 8 + 4];
                    #pragma unroll
                    for (int rr = 0; rr < 4; rr++) {
                        int4 pk = ((const int4*)sm->keys[rbase + rb + rr])[ci];
                        float2 f0 = __half22float2(*(__half2*)&pk.x);
                        float2 f1 = __half22float2(*(__half2*)&pk.y);
                        float2 f2 = __half22float2(*(__half2*)&pk.z);
                        float2 f3 = __half22float2(*(__half2*)&pk.w);
                        float s = f0.x * ha.x + f0.y * ha.y + f1.x * ha.z + f1.y * ha.w
                                + f2.x * hb.x + f2.y * hb.y + f3.x * hb.z + f3.y * hb.w;
                        if (rr == 0) a0 += s; else if (rr == 1) a1 += s;
                        else if (rr == 2) a2 += s; else a3 += s;
                    }
                }
                #pragma unroll
                for (int o = 16; o; o >>= 1) {
                    a0 += __shfl_xor_sync(0xffffffffu, a0, o);
                    a1 += __shfl_xor_sync(0xffffffffu, a1, o);
                    a2 += __shfl_xor_sync(0xffffffffu, a2, o);
                    a3 += __shfl_xor_sync(0xffffffffu, a3, o);
                }
                if (lane == 0) {
                    #pragma unroll
                    for (int rr = 0; rr < 4; rr++) {
                        int r = rbase + rb + rr;
                        float a = (rr == 0) ? a0 : (rr == 1) ? a1 : (rr == 2) ? a2 : a3;
                        float s = (sm->maskb[r] != 0.f) ? a * SCALE : -1.0e9f;
                        sm->sc[r]  = s;
                        sm->raw[r] = s;
                    }
                }
            }
        }
        __syncthreads();

        // ---- local softmax stats over 128 rows ----
        {
            float v = (tid < CHUNK) ? sm->sc[tid] : -3.4e38f;
            float m = wmax(v);
            if (lane == 0) sm->red[warp] = m;
            __syncthreads();
            if (tid < 32) {
                float x = (lane < NW) ? sm->red[lane] : -3.4e38f;
                x = wmax(x);
                if (lane == 0) sm->bc[0] = x;
            }
            __syncthreads();
            float mb = sm->bc[0];
            float e = 0.f;
            if (tid < CHUNK) { e = __expf(v - mb); sm->sc[tid] = e; }
            float s = wsum(e);
            if (lane == 0) sm->red[warp] = s;
            __syncthreads();
            if (tid < 32) {
                float x = (lane < NW) ? sm->red[lane] : 0.f;
                x = wsum(x);
                if (lane == 0) { __stcg(&g_pm[b], mb); __stcg(&g_ps[b], x); }
            }
            __syncthreads();
        }

        // ---- partial summary u_b = sum_j e_j * v_j (fp16 values from L2) ----
        {
            int dbase = tid & 63;        // int4 (8 halves) within the 512-dim row
            int rg = tid >> 6;           // 8 row-groups of 16 rows
            float acc[8];
            #pragma unroll
            for (int i = 0; i < 8; i++) acc[i] = 0.f;
            const int4* vp = (const int4*)g_vals + (size_t)(j0 + rg * 16) * 64 + dbase;
            #pragma unroll 4
            for (int rr = 0; rr < 16; rr++) {
                float e = sm->sc[rg * 16 + rr];
                int4 pv = __ldcg(vp); vp += 64;
                float2 f0 = __half22float2(*(__half2*)&pv.x);
                float2 f1 = __half22float2(*(__half2*)&pv.y);
                float2 f2 = __half22float2(*(__half2*)&pv.z);
                float2 f3 = __half22float2(*(__half2*)&pv.w);
                acc[0] += e * f0.x; acc[1] += e * f0.y;
                acc[2] += e * f1.x; acc[3] += e * f1.y;
                acc[4] += e * f2.x; acc[5] += e * f2.y;
                acc[6] += e * f3.x; acc[7] += e * f3.y;
            }
            float4* pp = (float4*)&sm->part[rg][dbase * 8];
            pp[0] = make_float4(acc[0], acc[1], acc[2], acc[3]);
            pp[1] = make_float4(acc[4], acc[5], acc[6], acc[7]);
            __syncthreads();
            float s = 0.f;
            #pragma unroll
            for (int g = 0; g < 8; g++) s += sm->part[g][tid];
            sm->u[tid] = s;
            __syncthreads();
        }

        // ---- z_b[k] = w_out[k,:512] . u_b (smem-cached w_out) ----
        for (int k = warp; k < VOCAB; k += NW) {
            float acc = 0.f;
            #pragma unroll
            for (int i = 0; i < 16; i++)
                acc += sm->u[lane + 32 * i] * sm->wout[k][lane + 32 * i];
            acc = wsum(acc);
            if (lane == 0) __stcg(&g_z[b][k], acc);
        }

        // ================= epoch sync e = t+1 =================
        __syncthreads();
        if (tid == 0) { __threadfence(); atomicAdd(&g_cnt[(t + 1) & 1], 1); }
        if (b == 0) {
            if (tid == 0) {
                while (*(volatile int*)&g_cnt[(t + 1) & 1] < NB) __nanosleep(32);
                atomicExch(&g_cnt[(t + 1) & 1], 0);
                __threadfence();
            }
            __syncthreads();
            // ---- serial combine ----
            if (warp == 0) {
                float m = -3.4e38f;
                for (int i = lane; i < NB; i += 32) m = fmaxf(m, __ldcg(&g_pm[i]));
                m = wmax(m);
                float sp = 0.f;
                for (int i = lane; i < NB; i += 32) {
                    float cc = __expf(__ldcg(&g_pm[i]) - m);
                    sm->c[i] = cc;
                    sp += cc * __ldcg(&g_ps[i]);
                }
                sp = wsum(sp);
                if (lane == 0) { sm->bc[0] = m; sm->bc[1] = sp; }
            }
            __syncthreads();
            float mg = sm->bc[0];
            float sg = sm->bc[1];
            float inv = 1.f / sg;
            for (int k = warp; k < VOCAB; k += NW) {
                float a1 = 0.f;
                #pragma unroll
                for (int i = lane; i < NB; i += 32) a1 += sm->c[i] * __ldcg(&g_z[i][k]);
                float a2 = 0.f;
                const float* wr = w_out + (size_t)k * 1024 + 512;
                #pragma unroll
                for (int d = lane; d < HID; d += 32) a2 += wr[d] * sm->h[d];
                a1 = wsum(a1);
                a2 = wsum(a2);
                if (lane == 0) sm->lg[k] = a1 * inv + a2 + b_out[k];
            }
            __syncthreads();
            if (tid < VOCAB) out[(size_t)t * VOCAB + tid] = sm->lg[tid];
            if (tid == 0) {
                int best = 0; float bv = sm->lg[0];
                #pragma unroll
                for (int k = 1; k < VOCAB; k++)
                    if (sm->lg[k] > bv) { bv = sm->lg[k]; best = k; }
                __stcg(&g_token, best);
                __stcg(&g_mg, mg);
                __stcg(&g_sg, sg);
                if (best == EOS && g_len == STEPS) g_len = t;
                if (t == STEPS - 1) out[OUT_LEN] = (float)g_len;
            }
            __syncthreads();
            if (tid == 0) { __threadfence(); atomicExch((int*)&g_done, t + 2); }
        }
        if (tid == 0) {
            while (g_done < t + 2) __nanosleep(32);
            __threadfence();
        }
        __syncthreads();
    }

    // ---- reset broadcast flag for the next graph replay ----
    gsync_full();
    if (b == 0 && tid == 0) atomicExch((int*)&g_done, 0);
}

extern "C" void kernel_launch(void* const* d_in, const int* in_sizes, int n_in,
                              void* d_out, int out_size) {
    const float* enc    = (const float*)d_in[0];
    const float* embed  = (const float*)d_in[2];
    const float* w_ih   = (const float*)d_in[3];
    const float* w_hh   = (const float*)d_in[4];
    const float* b_ih   = (const float*)d_in[5];
    const float* b_hh   = (const float*)d_in[6];
    const float* w_out  = (const float*)d_in[7];
    const float* b_out  = (const float*)d_in[8];
    float* out = (float*)d_out;

    int smem = (int)sizeof(SM);
    cudaFuncSetAttribute(decoder_kernel,
                         cudaFuncAttributeMaxDynamicSharedMemorySize, smem);
    decoder_kernel<<<NB, NT, smem>>>(enc, embed, w_ih, w_hh, b_ih, b_hh,
                                     w_out, b_out, out);
}

// round 4
// speedup vs baseline: 3.3632x; 2.0423x over previous
#include <cuda_runtime.h>
#include <cuda_fp16.h>
#include <math.h>

#define T_ENC  16384
#define HID    512
#define G3     1536
#define VOCAB  31
#define STEPS  100
#define EOS    29
#define NBW    128              // worker blocks
#define GRID   (NBW + 1)        // +1 dedicated combiner block
#define NT     512
#define NW     (NT/32)
#define CHUNK  (T_ENC/NBW)      // 128 rows per worker
#define SCALE  0.04419417382415922f

#define OUT_LEN (STEPS*VOCAB)
#define OUT_ATT (STEPS*VOCAB+1)

// ---------------- persistent device scratch ----------------
__device__ int4  g_vals[T_ENC * 64];     // fp16 values
__device__ float g_gx[VOCAB * G3];       // gx lookup table per token
__device__ float g_gh[2][G3];            // gh double-buffered
__device__ float g_part[NBW][32];        // per-block: z[0..30], sumexp at [31]
__device__ float g_inv;                  // 1/sumexp of current step
__device__ int   g_flag[NBW];            // worker arrival epochs (monotone)
__device__ volatile int g_done = 0;      // combiner broadcast: epoch | token<<8

// ---------------- smem layouts ----------------
struct __align__(16) SMW {               // worker (~216 KB)
    uint2  keys[CHUNK][128];   // fp16 keys, 1 KB/row
    float  wout[VOCAB][512];   // w_out[:, :512]
    float  part[8][512];       // summary partials
    float  h[512];
    float  u[512];
    float  sc[CHUNK];          // e = exp(score)  (0 if masked)
    float  maskb[CHUNK];
    float  red[NW];
    int    tok;
};
struct __align__(16) SMC {               // combiner
    float  wout_hi[VOCAB][512];  // w_out[:, 512:]
    float  h[512];
    float  a2[32];               // w_out_hi . h + b_out
    float  tot[16][32];
    int    tok;
};

__device__ __forceinline__ float wsum(float v) {
    #pragma unroll
    for (int o = 16; o; o >>= 1) v += __shfl_xor_sync(0xffffffffu, v, o);
    return v;
}

__global__ void __launch_bounds__(NT, 1)
decoder_kernel(const float* __restrict__ enc,
               const float* __restrict__ embed,
               const float* __restrict__ w_ih,
               const float* __restrict__ w_hh,
               const float* __restrict__ b_ih,
               const float* __restrict__ b_hh,
               const float* __restrict__ w_out,
               const float* __restrict__ b_out,
               float* __restrict__ out)
{
    extern __shared__ __align__(16) unsigned char smem_raw[];
    const int tid  = threadIdx.x;
    const int b    = blockIdx.x;
    const int lane = tid & 31;
    const int warp = tid >> 5;

    // ======================= COMBINER BLOCK =======================
    if (b == NBW) {
        SMC* sm = (SMC*)smem_raw;
        // setup: cache w_out hi half, init gh0 = b_hh (h0 = 0)
        for (int idx = tid; idx < VOCAB * 512; idx += NT) {
            int k = idx >> 9, d = idx & 511;
            sm->wout_hi[k][d] = w_out[(size_t)k * 1024 + 512 + d];
        }
        for (int i = tid; i < G3; i += NT) g_gh[0][i] = b_hh[i];
        if (tid == 0) sm->tok = EOS;
        int len = STEPS;                      // tracked by tid 0 only
        // wait for all workers' setup
        if (tid < NBW) {
            while (*(volatile int*)&g_flag[tid] < 1) {}
            __threadfence();
        }
        __syncthreads();
        if (tid == 0) { __threadfence(); g_done = 1 | (EOS << 8); }

        float hreg = 0.f;
        for (int t = 0; t < STEPS; t++) {
            const int p = t & 1;
            int tok = sm->tok;
            // redundant GRU -> h (needed for a2)
            {
                const float* gx = g_gx + (size_t)tok * G3;
                float ghr = __ldcg(&g_gh[p][tid]);
                float ghz = __ldcg(&g_gh[p][HID + tid]);
                float ghn = __ldcg(&g_gh[p][2 * HID + tid]);
                float r_ = 1.f / (1.f + expf(-(gx[tid] + ghr)));
                float z_ = 1.f / (1.f + expf(-(gx[HID + tid] + ghz)));
                float n_ = tanhf(gx[2 * HID + tid] + r_ * ghn);
                hreg = (1.f - z_) * n_ + z_ * hreg;
                sm->h[tid] = hreg;
            }
            __syncthreads();
            // a2[k] = w_out[k,512:] . h + b_out[k]   (while workers attend)
            for (int k = warp; k < VOCAB; k += NW) {
                float acc = 0.f;
                #pragma unroll
                for (int i = 0; i < 16; i++)
                    acc += sm->wout_hi[k][lane + 32 * i] * sm->h[lane + 32 * i];
                acc = wsum(acc);
                if (lane == 0) sm->a2[k] = acc + b_out[k];
            }
            // wait for all workers of step t
            if (tid < NBW) {
                while (*(volatile int*)&g_flag[tid] < t + 2) {}
                __threadfence();
            }
            __syncthreads();
            // sum partials: thread (grp, k) sums 8 blocks
            {
                int k = tid & 31, grp = tid >> 5;
                float s = 0.f;
                #pragma unroll
                for (int i = 0; i < 8; i++)
                    s += __ldcg(&g_part[grp * 8 + i][k]);
                sm->tot[grp][k] = s;
            }
            __syncthreads();
            if (tid < 32) {
                int k = tid;
                float s = 0.f;
                #pragma unroll
                for (int g = 0; g < 16; g++) s += sm->tot[g][k];
                float sg  = __shfl_sync(0xffffffffu, s, 31);   // col 31 = sumexp
                float inv = 1.f / sg;
                float lg  = (k < VOCAB) ? s * inv + sm->a2[k] : -3.4e38f;
                if (k < VOCAB) out[(size_t)t * VOCAB + k] = lg;
                // argmax (first max wins)
                float bv = lg; int bi = k;
                #pragma unroll
                for (int o = 16; o; o >>= 1) {
                    float ov = __shfl_xor_sync(0xffffffffu, bv, o);
                    int   oi = __shfl_xor_sync(0xffffffffu, bi, o);
                    if (ov > bv || (ov == bv && oi < bi)) { bv = ov; bi = oi; }
                }
                if (k == 0) {
                    sm->tok = bi;
                    __stcg(&g_inv, inv);
                    if (bi == EOS && len == STEPS) len = t;
                    if (t == STEPS - 1) out[OUT_LEN] = (float)len;
                    __threadfence();
                    g_done = (t + 2) | (bi << 8);
                }
            }
            __syncthreads();
        }
        // teardown: wait final acks, reset sync state for next graph replay
        if (tid < NBW) {
            while (*(volatile int*)&g_flag[tid] < STEPS + 2) {}
        }
        __syncthreads();
        if (tid < NBW) g_flag[tid] = 0;
        if (tid == 0) { g_done = 0; __threadfence(); }
        return;
    }

    // ======================= WORKER BLOCKS =======================
    SMW* sm = (SMW*)smem_raw;
    const int j0 = b * CHUNK;

    float whh[16];
    float bhh = 0.f;

    // ---- setup: keys->smem fp16, values->global fp16, mask ----
    for (int r = warp; r < CHUNK; r += NW) {
        int j = j0 + r;
        const float4* src = (const float4*)(enc + (size_t)j * 1024);
        bool anyne = false;
        #pragma unroll
        for (int c = lane; c < 128; c += 32) {
            float4 f = src[c];
            anyne |= (f.x != 30.f) | (f.y != 30.f) | (f.z != 30.f) | (f.w != 30.f);
            __half2 a = __floats2half2_rn(f.x, f.y);
            __half2 bb = __floats2half2_rn(f.z, f.w);
            uint2 pk; pk.x = *(unsigned*)&a; pk.y = *(unsigned*)&bb;
            sm->keys[r][c] = pk;
            float4 v = src[128 + c];
            __half2 c0 = __floats2half2_rn(v.x, v.y);
            __half2 c1 = __floats2half2_rn(v.z, v.w);
            uint2 pv; pv.x = *(unsigned*)&c0; pv.y = *(unsigned*)&c1;
            ((uint2*)g_vals)[(size_t)j * 128 + c] = pv;
        }
        bool msk = __any_sync(0xffffffffu, anyne);
        if (lane == 0) sm->maskb[r] = msk ? 1.f : 0.f;
    }
    // w_out lo half -> smem
    for (int idx = tid; idx < VOCAB * 512; idx += NT) {
        int k = idx >> 9, d = idx & 511;
        sm->wout[k][d] = w_out[(size_t)k * 1024 + d];
    }
    // w_hh rows -> regs (warp w<12 owns row b*12+w)
    if (warp < 12) {
        int o = b * 12 + warp;
        const float* wr = w_hh + (size_t)o * HID;
        #pragma unroll
        for (int i = 0; i < 16; i++) whh[i] = wr[lane + 32 * i];
        bhh = b_hh[o];
    }
    // gx table portion
    {
        int wg = b * NW + warp;
        for (int r = wg; r < G3; r += NBW * NW) {
            const float* wr = w_ih + (size_t)r * HID;
            float wreg[16];
            #pragma unroll
            for (int i = 0; i < 16; i++) wreg[i] = wr[lane + 32 * i];
            float bias = b_ih[r];
            for (int v = 0; v < VOCAB; v++) {
                const float* er = embed + (size_t)v * HID;
                float acc = 0.f;
                #pragma unroll
                for (int i = 0; i < 16; i++) acc += wreg[i] * er[lane + 32 * i];
                acc = wsum(acc);
                if (lane == 0) g_gx[v * G3 + r] = acc + bias;
            }
        }
    }
    __syncthreads();
    if (tid == 0) { __threadfence(); __stcg(&g_flag[b], 1); }

    // ---- decode loop ----
    float hreg = 0.f;
    for (int t = 0; t <= STEPS; t++) {
        // wait for epoch t+1 broadcast (carries the token)
        if (tid == 0) {
            int d;
            do { d = g_done; } while ((d & 0xff) < t + 1);
            sm->tok = d >> 8;
        }
        __syncthreads();

        // attention output of step t-1 (sc still holds its e values)
        if (t > 0 && tid < CHUNK) {
            float inv = __ldcg(&g_inv);
            out[OUT_ATT + (size_t)(t - 1) * T_ENC + j0 + tid] = sm->sc[tid] * inv;
        }
        if (t == STEPS) break;

        const int p = t & 1, q = p ^ 1;
        // GRU combine
        {
            int tok = sm->tok;
            const float* gx = g_gx + (size_t)tok * G3;
            float ghr = __ldcg(&g_gh[p][tid]);
            float ghz = __ldcg(&g_gh[p][HID + tid]);
            float ghn = __ldcg(&g_gh[p][2 * HID + tid]);
            float r_ = 1.f / (1.f + expf(-(gx[tid] + ghr)));
            float z_ = 1.f / (1.f + expf(-(gx[HID + tid] + ghz)));
            float n_ = tanhf(gx[2 * HID + tid] + r_ * ghn);
            hreg = (1.f - z_) * n_ + z_ * hreg;
            sm->h[tid] = hreg;
        }
        __syncthreads();

        // gh(t+1) for next step: 12 rows per block, weights in regs
        if (warp < 12) {
            float acc = 0.f;
            #pragma unroll
            for (int i = 0; i < 16; i++) acc += whh[i] * sm->h[lane + 32 * i];
            acc = wsum(acc);
            if (lane == 0) __stcg(&g_gh[q][b * 12 + warp], acc + bhh);
        }

        // scores -> e = exp(scale*dot) (no max shift; bounded), masked -> 0
        {
            int rbase = warp * 8;
            #pragma unroll
            for (int rb = 0; rb < 8; rb += 4) {
                float a0 = 0.f, a1 = 0.f, a2 = 0.f, a3 = 0.f;
                #pragma unroll
                for (int c = 0; c < 2; c++) {
                    int ci = lane + 32 * c;
                    float4 ha = *(const float4*)&sm->h[ci * 8];
                    float4 hb = *(const float4*)&sm->h[ci * 8 + 4];
                    #pragma unroll
                    for (int rr = 0; rr < 4; rr++) {
                        int4 pk = ((const int4*)sm->keys[rbase + rb + rr])[ci];
                        float2 f0 = __half22float2(*(__half2*)&pk.x);
                        float2 f1 = __half22float2(*(__half2*)&pk.y);
                        float2 f2 = __half22float2(*(__half2*)&pk.z);
                        float2 f3 = __half22float2(*(__half2*)&pk.w);
                        float s = f0.x * ha.x + f0.y * ha.y + f1.x * ha.z + f1.y * ha.w
                                + f2.x * hb.x + f2.y * hb.y + f3.x * hb.z + f3.y * hb.w;
                        if (rr == 0) a0 += s; else if (rr == 1) a1 += s;
                        else if (rr == 2) a2 += s; else a3 += s;
                    }
                }
                #pragma unroll
                for (int o = 16; o; o >>= 1) {
                    a0 += __shfl_xor_sync(0xffffffffu, a0, o);
                    a1 += __shfl_xor_sync(0xffffffffu, a1, o);
                    a2 += __shfl_xor_sync(0xffffffffu, a2, o);
                    a3 += __shfl_xor_sync(0xffffffffu, a3, o);
                }
                if (lane == 0) {
                    #pragma unroll
                    for (int rr = 0; rr < 4; rr++) {
                        int r = rbase + rb + rr;
                        float a = (rr == 0) ? a0 : (rr == 1) ? a1 : (rr == 2) ? a2 : a3;
                        sm->sc[r] = sm->maskb[r] * __expf(a * SCALE);
                    }
                }
            }
        }
        __syncthreads();

        // local sumexp partials (warps 0-3)
        if (tid < CHUNK) {
            float e = sm->sc[tid];
            float s = wsum(e);
            if (lane == 0) sm->red[warp] = s;
        }

        // partial summary u = sum_j e_j * v_j  (fp16 values streamed from L2)
        {
            int dbase = tid & 63;
            int rg = tid >> 6;
            float acc[8];
            #pragma unroll
            for (int i = 0; i < 8; i++) acc[i] = 0.f;
            const int4* vp = (const int4*)g_vals + (size_t)(j0 + rg * 16) * 64 + dbase;
            #pragma unroll 4
            for (int rr = 0; rr < 16; rr++) {
                float e = sm->sc[rg * 16 + rr];
                int4 pv = __ldcg(vp); vp += 64;
                float2 f0 = __half22float2(*(__half2*)&pv.x);
                float2 f1 = __half22float2(*(__half2*)&pv.y);
                float2 f2 = __half22float2(*(__half2*)&pv.z);
                float2 f3 = __half22float2(*(__half2*)&pv.w);
                acc[0] += e * f0.x; acc[1] += e * f0.y;
                acc[2] += e * f1.x; acc[3] += e * f1.y;
                acc[4] += e * f2.x; acc[5] += e * f2.y;
                acc[6] += e * f3.x; acc[7] += e * f3.y;
            }
            float4* pp = (float4*)&sm->part[rg][dbase * 8];
            pp[0] = make_float4(acc[0], acc[1], acc[2], acc[3]);
            pp[1] = make_float4(acc[4], acc[5], acc[6], acc[7]);
            __syncthreads();
            float s = 0.f;
            #pragma unroll
            for (int g = 0; g < 8; g++) s += sm->part[g][tid];
            sm->u[tid] = s;
            __syncthreads();
        }

        // z[k] = w_out[k,:512] . u  -> g_part[b][k]; sumexp -> g_part[b][31]
        for (int k = warp; k < VOCAB; k += NW) {
            float acc = 0.f;
            #pragma unroll
            for (int i = 0; i < 16; i++)
                acc += sm->u[lane + 32 * i] * sm->wout[k][lane + 32 * i];
            acc = wsum(acc);
            if (lane == 0) __stcg(&g_part[b][k], acc);
        }
        if (tid == 0) {
            float ps = sm->red[0] + sm->red[1] + sm->red[2] + sm->red[3];
            __stcg(&g_part[b][31], ps);
        }
        __syncthreads();
        if (tid == 0) { __threadfence(); __stcg(&g_flag[b], t + 2); }
    }
    // final ack so combiner can reset state
    __syncthreads();
    if (tid == 0) { __threadfence(); __stcg(&g_flag[b], STEPS + 2); }
}

extern "C" void kernel_launch(void* const* d_in, const int* in_sizes, int n_in,
                              void* d_out, int out_size) {
    const float* enc    = (const float*)d_in[0];
    const float* embed  = (const float*)d_in[2];
    const float* w_ih   = (const float*)d_in[3];
    const float* w_hh   = (const float*)d_in[4];
    const float* b_ih   = (const float*)d_in[5];
    const float* b_hh   = (const float*)d_in[6];
    const float* w_out  = (const float*)d_in[7];
    const float* b_out  = (const float*)d_in[8];
    float* out = (float*)d_out;

    int smem = (int)sizeof(SMW);
    cudaFuncSetAttribute(decoder_kernel,
                         cudaFuncAttributeMaxDynamicSharedMemorySize, smem);
    decoder_kernel<<<GRID, NT, smem>>>(enc, embed, w_ih, w_hh, b_ih, b_hh,
                                       w_out, b_out, out);
}

// round 5
// speedup vs baseline: 4.2138x; 1.2529x over previous
#include <cuda_runtime.h>
#include <cuda_fp16.h>
#include <math.h>

#define T_ENC  16384
#define HID    512
#define G3     1536
#define VOCAB  31
#define STEPS  100
#define EOS    29
#define NBW    128              // worker blocks
#define GRID   (NBW + 1)        // +1 combiner block
#define NT     512
#define NW     (NT/32)          // 16 warps
#define CHUNK  (T_ENC/NBW)      // 128 rows per worker
#define SCALE  0.04419417382415922f

#define OUT_LEN (STEPS*VOCAB)
#define OUT_ATT (STEPS*VOCAB+1)

// ---------------- persistent device scratch ----------------
__device__ float g_pv[T_ENC * 32];       // PV[j][k] = w_out[k,:512].v_j ; PV[j][31]=1
__device__ float g_gx[VOCAB * G3];       // gx table per token
__device__ float g_gh[2][G3];            // gh double-buffered
__device__ float g_part[NBW][32];        // per-block z[0..30], sumexp at [31]
__device__ float g_inv;                  // 1/sumexp of current step
__device__ int   g_flag[NBW];            // worker arrival epochs
__device__ volatile int g_done = 0;      // combiner broadcast: epoch | token<<8

// ---------------- smem layouts ----------------
struct __align__(16) SMW {               // worker (~136 KB)
    uint2  keys[CHUNK][128];   // fp16 keys, 1 KB/row
    float  h[HID];
    float  sc[CHUNK];          // e = exp(score) (0 if masked)
    float  maskb[CHUNK];
    float  zred[NW][32];
    int    tok;
};
struct __align__(16) SMC {               // combiner
    float  wout_hi[VOCAB][512];
    float  h[HID];
    float  a2[32];
    float  tot[16][32];
    int    tok;
};

__device__ __forceinline__ float wsum(float v) {
    #pragma unroll
    for (int o = 16; o; o >>= 1) v += __shfl_xor_sync(0xffffffffu, v, o);
    return v;
}

// GRU cell for dim `tid` (identical code on workers and combiner)
__device__ __forceinline__ float gru_dim(const float* __restrict__ gx,
                                         const float* __restrict__ ghbuf,
                                         int tid, float hprev) {
    float ghr = __ldcg(&ghbuf[tid]);
    float ghz = __ldcg(&ghbuf[HID + tid]);
    float ghn = __ldcg(&ghbuf[2 * HID + tid]);
    float xr = gx[tid] + ghr;
    float xz = gx[HID + tid] + ghz;
    float r_ = __fdividef(1.f, 1.f + __expf(-xr));
    float z_ = __fdividef(1.f, 1.f + __expf(-xz));
    float nx = gx[2 * HID + tid] + r_ * ghn;
    nx = fminf(fmaxf(nx, -15.f), 15.f);
    float t2 = __expf(2.f * nx);
    float n_ = __fdividef(t2 - 1.f, t2 + 1.f);
    return (1.f - z_) * n_ + z_ * hprev;
}

__global__ void __launch_bounds__(NT, 1)
decoder_kernel(const float* __restrict__ enc,
               const float* __restrict__ embed,
               const float* __restrict__ w_ih,
               const float* __restrict__ w_hh,
               const float* __restrict__ b_ih,
               const float* __restrict__ b_hh,
               const float* __restrict__ w_out,
               const float* __restrict__ b_out,
               float* __restrict__ out)
{
    extern __shared__ __align__(16) unsigned char smem_raw[];
    const int tid  = threadIdx.x;
    const int b    = blockIdx.x;
    const int lane = tid & 31;
    const int warp = tid >> 5;

    // ======================= COMBINER BLOCK =======================
    if (b == NBW) {
        SMC* sm = (SMC*)smem_raw;
        for (int idx = tid; idx < VOCAB * 512; idx += NT) {
            int k = idx >> 9, d = idx & 511;
            sm->wout_hi[k][d] = w_out[(size_t)k * 1024 + 512 + d];
        }
        for (int i = tid; i < G3; i += NT) g_gh[0][i] = b_hh[i];
        if (tid == 0) sm->tok = EOS;
        int len = STEPS;
        if (tid < NBW) {
            while (*(volatile int*)&g_flag[tid] < 1) {}
            __threadfence();
        }
        __syncthreads();
        if (tid == 0) { __threadfence(); g_done = 1 | (EOS << 8); }

        float hreg = 0.f;
        for (int t = 0; t < STEPS; t++) {
            const int p = t & 1;
            const float* gx = g_gx + (size_t)sm->tok * G3;
            hreg = gru_dim(gx, g_gh[p], tid, hreg);
            sm->h[tid] = hreg;
            __syncthreads();
            // a2[k] = w_out[k,512:].h + b_out[k] (overlapped with workers)
            for (int k = warp; k < VOCAB; k += NW) {
                float acc = 0.f;
                #pragma unroll
                for (int i = 0; i < 16; i++)
                    acc += sm->wout_hi[k][lane + 32 * i] * sm->h[lane + 32 * i];
                acc = wsum(acc);
                if (lane == 0) sm->a2[k] = acc + b_out[k];
            }
            // wait for all workers of step t
            if (tid < NBW) {
                while (*(volatile int*)&g_flag[tid] < t + 2) {}
                __threadfence();
            }
            __syncthreads();
            // sum per-block partials
            {
                int k = tid & 31, grp = tid >> 5;
                float s = 0.f;
                #pragma unroll
                for (int i = 0; i < 8; i++)
                    s += __ldcg(&g_part[grp * 8 + i][k]);
                sm->tot[grp][k] = s;
            }
            __syncthreads();
            if (tid < 32) {
                int k = tid;
                float s = 0.f;
                #pragma unroll
                for (int g = 0; g < 16; g++) s += sm->tot[g][k];
                float sg  = __shfl_sync(0xffffffffu, s, 31);
                float inv = __fdividef(1.f, sg);
                float lg  = (k < VOCAB) ? s * inv + sm->a2[k] : -3.4e38f;
                if (k < VOCAB) out[(size_t)t * VOCAB + k] = lg;
                float bv = lg; int bi = k;
                #pragma unroll
                for (int o = 16; o; o >>= 1) {
                    float ov = __shfl_xor_sync(0xffffffffu, bv, o);
                    int   oi = __shfl_xor_sync(0xffffffffu, bi, o);
                    if (ov > bv || (ov == bv && oi < bi)) { bv = ov; bi = oi; }
                }
                if (k == 0) {
                    sm->tok = bi;
                    __stcg(&g_inv, inv);
                    if (bi == EOS && len == STEPS) len = t;
                    if (t == STEPS - 1) out[OUT_LEN] = (float)len;
                    __threadfence();
                    g_done = (t + 2) | (bi << 8);
                }
            }
            __syncthreads();
        }
        if (tid < NBW) {
            while (*(volatile int*)&g_flag[tid] < STEPS + 2) {}
        }
        __syncthreads();
        if (tid < NBW) g_flag[tid] = 0;
        if (tid == 0) { g_done = 0; __threadfence(); }
        return;
    }

    // ======================= WORKER BLOCKS =======================
    SMW* sm = (SMW*)smem_raw;
    const int j0 = b * CHUNK;
    const int rbase = warp * 8;

    float whh[16];
    float bhh = 0.f;

    // ---- setup: keys -> smem fp16, mask ----
    for (int r = warp; r < CHUNK; r += NW) {
        int j = j0 + r;
        const float4* src = (const float4*)(enc + (size_t)j * 1024);
        bool anyne = false;
        #pragma unroll
        for (int c = lane; c < 128; c += 32) {
            float4 f = src[c];
            anyne |= (f.x != 30.f) | (f.y != 30.f) | (f.z != 30.f) | (f.w != 30.f);
            __half2 a = __floats2half2_rn(f.x, f.y);
            __half2 bb = __floats2half2_rn(f.z, f.w);
            uint2 pk; pk.x = *(unsigned*)&a; pk.y = *(unsigned*)&bb;
            sm->keys[r][c] = pk;
        }
        bool msk = __any_sync(0xffffffffu, anyne);
        if (lane == 0) sm->maskb[r] = msk ? 1.f : 0.f;
    }
    // ---- setup: PV[j][k] = w_out[k,:512].v_j ; PV[j][31] = 1 ----
    for (int pp = 0; pp < 4; pp++) {
        int r0 = j0 + rbase + pp * 2;
        float acc0[VOCAB], acc1[VOCAB];
        #pragma unroll
        for (int k = 0; k < VOCAB; k++) { acc0[k] = 0.f; acc1[k] = 0.f; }
        const float* v0p = enc + (size_t)r0 * 1024 + 512;
        const float* v1p = v0p + 1024;
        for (int d0 = 0; d0 < 512; d0 += 32) {
            float v0 = __ldg(v0p + d0 + lane);
            float v1 = __ldg(v1p + d0 + lane);
            #pragma unroll
            for (int k = 0; k < VOCAB; k++) {
                float w = __ldg(&w_out[(size_t)k * 1024 + d0 + lane]);
                acc0[k] += v0 * w;
                acc1[k] += v1 * w;
            }
        }
        #pragma unroll
        for (int k = 0; k < VOCAB; k++) {
            float s0 = wsum(acc0[k]);
            float s1 = wsum(acc1[k]);
            if (lane == 0) {
                g_pv[(size_t)r0 * 32 + k]       = s0;
                g_pv[(size_t)(r0 + 1) * 32 + k] = s1;
            }
        }
        if (lane == 0) {
            g_pv[(size_t)r0 * 32 + 31]       = 1.f;
            g_pv[(size_t)(r0 + 1) * 32 + 31] = 1.f;
        }
    }
    // ---- setup: w_hh rows -> regs (warp w<12 owns row b*12+w) ----
    if (warp < 12) {
        int o = b * 12 + warp;
        const float* wr = w_hh + (size_t)o * HID;
        #pragma unroll
        for (int i = 0; i < 16; i++) whh[i] = wr[lane + 32 * i];
        bhh = b_hh[o];
    }
    // ---- setup: gx table portion ----
    {
        int wg = b * NW + warp;
        for (int r = wg; r < G3; r += NBW * NW) {
            const float* wr = w_ih + (size_t)r * HID;
            float wreg[16];
            #pragma unroll
            for (int i = 0; i < 16; i++) wreg[i] = wr[lane + 32 * i];
            float bias = b_ih[r];
            for (int v = 0; v < VOCAB; v++) {
                const float* er = embed + (size_t)v * HID;
                float acc = 0.f;
                #pragma unroll
                for (int i = 0; i < 16; i++) acc += wreg[i] * er[lane + 32 * i];
                acc = wsum(acc);
                if (lane == 0) g_gx[v * G3 + r] = acc + bias;
            }
        }
    }
    __syncthreads();
    if (tid == 0) { __threadfence(); __stcg(&g_flag[b], 1); }

    // ---- decode loop ----
    float hreg = 0.f;
    for (int t = 0; t <= STEPS; t++) {
        if (tid == 0) {
            int d;
            do { d = g_done; } while ((d & 0xff) < t + 1);
            sm->tok = d >> 8;
        }
        __syncthreads();

        // attention output of step t-1
        if (t > 0 && tid < CHUNK) {
            float inv = __ldcg(&g_inv);
            out[OUT_ATT + (size_t)(t - 1) * T_ENC + j0 + tid] = sm->sc[tid] * inv;
        }
        if (t == STEPS) break;

        const int p = t & 1, q = p ^ 1;
        // GRU combine (h[tid] per thread)
        {
            const float* gx = g_gx + (size_t)sm->tok * G3;
            hreg = gru_dim(gx, g_gh[p], tid, hreg);
            sm->h[tid] = hreg;
        }
        __syncthreads();

        // gh(t+1): 12 rows per block, weights in regs; fence for release
        if (warp < 12) {
            float acc = 0.f;
            #pragma unroll
            for (int i = 0; i < 16; i++) acc += whh[i] * sm->h[lane + 32 * i];
            acc = wsum(acc);
            if (lane == 0) __stcg(&g_gh[q][b * 12 + warp], acc + bhh);
            __threadfence();
        }

        // ---- fused scores + z accumulation (PV prefetched) ----
        float zacc = 0.f;
        {
            float pv[8];
            #pragma unroll
            for (int r = 0; r < 8; r++)
                pv[r] = __ldcg(&g_pv[(size_t)(j0 + rbase + r) * 32 + lane]);

            #pragma unroll
            for (int rb = 0; rb < 8; rb += 4) {
                float a0 = 0.f, a1 = 0.f, a2 = 0.f, a3 = 0.f;
                #pragma unroll
                for (int c = 0; c < 2; c++) {
                    int ci = lane + 32 * c;
                    float4 ha = *(const float4*)&sm->h[ci * 8];
                    float4 hb = *(const float4*)&sm->h[ci * 8 + 4];
                    #pragma unroll
                    for (int rr = 0; rr < 4; rr++) {
                        int4 pk = ((const int4*)sm->keys[rbase + rb + rr])[ci];
                        float2 f0 = __half22float2(*(__half2*)&pk.x);
                        float2 f1 = __half22float2(*(__half2*)&pk.y);
                        float2 f2 = __half22float2(*(__half2*)&pk.z);
                        float2 f3 = __half22float2(*(__half2*)&pk.w);
                        float s = f0.x * ha.x + f0.y * ha.y + f1.x * ha.z + f1.y * ha.w
                                + f2.x * hb.x + f2.y * hb.y + f3.x * hb.z + f3.y * hb.w;
                        if (rr == 0) a0 += s; else if (rr == 1) a1 += s;
                        else if (rr == 2) a2 += s; else a3 += s;
                    }
                }
                #pragma unroll
                for (int o = 16; o; o >>= 1) {
                    a0 += __shfl_xor_sync(0xffffffffu, a0, o);
                    a1 += __shfl_xor_sync(0xffffffffu, a1, o);
                    a2 += __shfl_xor_sync(0xffffffffu, a2, o);
                    a3 += __shfl_xor_sync(0xffffffffu, a3, o);
                }
                #pragma unroll
                for (int rr = 0; rr < 4; rr++) {
                    int r = rbase + rb + rr;
                    float a = (rr == 0) ? a0 : (rr == 1) ? a1 : (rr == 2) ? a2 : a3;
                    float e = sm->maskb[r] * __expf(a * SCALE);
                    if (lane == rb + rr) sm->sc[r] = e;   // for attn output
                    zacc += e * pv[rb + rr];              // k = lane (31 = sumexp)
                }
            }
            sm->zred[warp][lane] = zacc;
        }
        __syncthreads();

        // cross-warp z reduce -> g_part[b][k], then flag (warp 0 only)
        if (warp == 0) {
            float s = 0.f;
            #pragma unroll
            for (int w = 0; w < NW; w++) s += sm->zred[w][lane];
            __stcg(&g_part[b][lane], s);
            __threadfence();
            if (lane == 0) __stcg(&g_flag[b], t + 2);
        }
    }
    __syncthreads();
    if (tid == 0) { __threadfence(); __stcg(&g_flag[b], STEPS + 2); }
}

extern "C" void kernel_launch(void* const* d_in, const int* in_sizes, int n_in,
                              void* d_out, int out_size) {
    const float* enc    = (const float*)d_in[0];
    const float* embed  = (const float*)d_in[2];
    const float* w_ih   = (const float*)d_in[3];
    const float* w_hh   = (const float*)d_in[4];
    const float* b_ih   = (const float*)d_in[5];
    const float* b_hh   = (const float*)d_in[6];
    const float* w_out  = (const float*)d_in[7];
    const float* b_out  = (const float*)d_in[8];
    float* out = (float*)d_out;

    int smem = (int)sizeof(SMW);
    cudaFuncSetAttribute(decoder_kernel,
                         cudaFuncAttributeMaxDynamicSharedMemorySize, smem);
    decoder_kernel<<<GRID, NT, smem>>>(enc, embed, w_ih, w_hh, b_ih, b_hh,
                                       w_out, b_out, out);
}

// round 6
// speedup vs baseline: 4.8329x; 1.1469x over previous
#include <cuda_runtime.h>
#include <cuda_fp16.h>
#include <math.h>

#define T_ENC  16384
#define HID    512
#define G3     1536
#define VOCAB  31
#define STEPS  100
#define EOS    29
#define NBW    128              // worker blocks (all blocks are workers now)
#define NT     512
#define NW     (NT/32)          // 16 warps
#define CHUNK  (T_ENC/NBW)      // 128 rows per block
#define SCALE  0.04419417382415922f

#define OUT_LEN (STEPS*VOCAB)
#define OUT_ATT (STEPS*VOCAB+1)

// ---------------- persistent device scratch ----------------
__device__ float g_pv[T_ENC * 32];       // PV[j][k] = w_out[k,:512].v_j ; PV[j][31]=1
__device__ float g_gx[VOCAB * G3];       // gx table per token
__device__ float g_gh[2][G3];            // gh double-buffered by step parity
__device__ float g_part[2][NBW][32];     // parity-buffered per-block partials
__device__ int   g_arrive = 0;           // single monotone arrival counter

// ---------------- smem layout (~202 KB) ----------------
struct __align__(16) SMW {
    uint2  keys[CHUNK][128];     // fp16 keys, 1 KB/row  (128 KB)
    float  wout_hi[VOCAB][512];  // w_out[:, 512:]       (62 KB)
    float  h[HID];
    float  sc[CHUNK];            // e = exp(score) (0 if masked)
    float  maskb[CHUNK];
    float  zred[NW][32];
    float  tot[16][32];
    float  a2[32];
    float  inv;
    int    tok;
};

__device__ __forceinline__ float wsum(float v) {
    #pragma unroll
    for (int o = 16; o; o >>= 1) v += __shfl_xor_sync(0xffffffffu, v, o);
    return v;
}

// GRU cell for dim `tid` — identical deterministic code on every block
__device__ __forceinline__ float gru_dim(const float* __restrict__ gx,
                                         const float* __restrict__ ghbuf,
                                         int tid, float hprev) {
    float ghr = __ldcg(&ghbuf[tid]);
    float ghz = __ldcg(&ghbuf[HID + tid]);
    float ghn = __ldcg(&ghbuf[2 * HID + tid]);
    float xr = gx[tid] + ghr;
    float xz = gx[HID + tid] + ghz;
    float r_ = __fdividef(1.f, 1.f + __expf(-xr));
    float z_ = __fdividef(1.f, 1.f + __expf(-xz));
    float nx = gx[2 * HID + tid] + r_ * ghn;
    nx = fminf(fmaxf(nx, -15.f), 15.f);
    float t2 = __expf(2.f * nx);
    float n_ = __fdividef(t2 - 1.f, t2 + 1.f);
    return (1.f - z_) * n_ + z_ * hprev;
}

__global__ void __launch_bounds__(NT, 1)
decoder_kernel(const float* __restrict__ enc,
               const float* __restrict__ embed,
               const float* __restrict__ w_ih,
               const float* __restrict__ w_hh,
               const float* __restrict__ b_ih,
               const float* __restrict__ b_hh,
               const float* __restrict__ w_out,
               const float* __restrict__ b_out,
               float* __restrict__ out)
{
    extern __shared__ __align__(16) unsigned char smem_raw[];
    SMW* sm = (SMW*)smem_raw;

    const int tid  = threadIdx.x;
    const int b    = blockIdx.x;
    const int lane = tid & 31;
    const int warp = tid >> 5;
    const int j0   = b * CHUNK;
    const int rbase = warp * 8;

    float whh[16];
    float bhh = 0.f;

    // ================= setup =================
    // keys -> smem fp16, mask
    for (int r = warp; r < CHUNK; r += NW) {
        int j = j0 + r;
        const float4* src = (const float4*)(enc + (size_t)j * 1024);
        bool anyne = false;
        #pragma unroll
        for (int c = lane; c < 128; c += 32) {
            float4 f = src[c];
            anyne |= (f.x != 30.f) | (f.y != 30.f) | (f.z != 30.f) | (f.w != 30.f);
            __half2 a = __floats2half2_rn(f.x, f.y);
            __half2 bb = __floats2half2_rn(f.z, f.w);
            uint2 pk; pk.x = *(unsigned*)&a; pk.y = *(unsigned*)&bb;
            sm->keys[r][c] = pk;
        }
        bool msk = __any_sync(0xffffffffu, anyne);
        if (lane == 0) sm->maskb[r] = msk ? 1.f : 0.f;
    }
    // PV[j][k] = w_out[k,:512].v_j ; PV[j][31] = 1   (own chunk rows)
    for (int pp = 0; pp < 4; pp++) {
        int r0 = j0 + rbase + pp * 2;
        float acc0[VOCAB], acc1[VOCAB];
        #pragma unroll
        for (int k = 0; k < VOCAB; k++) { acc0[k] = 0.f; acc1[k] = 0.f; }
        const float* v0p = enc + (size_t)r0 * 1024 + 512;
        const float* v1p = v0p + 1024;
        for (int d0 = 0; d0 < 512; d0 += 32) {
            float v0 = __ldg(v0p + d0 + lane);
            float v1 = __ldg(v1p + d0 + lane);
            #pragma unroll
            for (int k = 0; k < VOCAB; k++) {
                float w = __ldg(&w_out[(size_t)k * 1024 + d0 + lane]);
                acc0[k] += v0 * w;
                acc1[k] += v1 * w;
            }
        }
        #pragma unroll
        for (int k = 0; k < VOCAB; k++) {
            float s0 = wsum(acc0[k]);
            float s1 = wsum(acc1[k]);
            if (lane == 0) {
                g_pv[(size_t)r0 * 32 + k]       = s0;
                g_pv[(size_t)(r0 + 1) * 32 + k] = s1;
            }
        }
        if (lane == 0) {
            g_pv[(size_t)r0 * 32 + 31]       = 1.f;
            g_pv[(size_t)(r0 + 1) * 32 + 31] = 1.f;
        }
    }
    // w_out hi half -> smem
    for (int idx = tid; idx < VOCAB * 512; idx += NT) {
        int k = idx >> 9, d = idx & 511;
        sm->wout_hi[k][d] = w_out[(size_t)k * 1024 + 512 + d];
    }
    // w_hh rows -> regs (warp w<12 owns row b*12+w)
    if (warp < 12) {
        int o = b * 12 + warp;
        const float* wr = w_hh + (size_t)o * HID;
        #pragma unroll
        for (int i = 0; i < 16; i++) whh[i] = wr[lane + 32 * i];
        bhh = b_hh[o];
    }
    // gx table portion
    {
        int wg = b * NW + warp;
        for (int r = wg; r < G3; r += NBW * NW) {
            const float* wr = w_ih + (size_t)r * HID;
            float wreg[16];
            #pragma unroll
            for (int i = 0; i < 16; i++) wreg[i] = wr[lane + 32 * i];
            float bias = b_ih[r];
            for (int v = 0; v < VOCAB; v++) {
                const float* er = embed + (size_t)v * HID;
                float acc = 0.f;
                #pragma unroll
                for (int i = 0; i < 16; i++) acc += wreg[i] * er[lane + 32 * i];
                acc = wsum(acc);
                if (lane == 0) g_gx[v * G3 + r] = acc + bias;
            }
        }
    }
    // gh[0] = b_hh (h0 = 0): block 0 writes it
    if (b == 0)
        for (int i = tid; i < G3; i += NT) __stcg(&g_gh[0][i], b_hh[i]);
    if (tid == 0) sm->tok = EOS;
    __syncthreads();
    // epoch 1 barrier
    if (tid == 0) {
        __threadfence();
        atomicAdd(&g_arrive, 1);
        while (*(volatile int*)&g_arrive < NBW) {}
    }
    __syncthreads();

    // PV registers for this warp's 8 rows (step-invariant)
    float pv[8];
    #pragma unroll
    for (int r = 0; r < 8; r++)
        pv[r] = __ldcg(&g_pv[(size_t)(j0 + rbase + r) * 32 + lane]);

    // ================= decode loop =================
    float hreg = 0.f;
    int len = STEPS;               // meaningful on b==0 lane-path only

    for (int t = 0; t < STEPS; t++) {
        const int p = t & 1, q = p ^ 1;

        // ---- GRU (h[tid] per thread) ----
        {
            const float* gx = g_gx + (size_t)sm->tok * G3;
            hreg = gru_dim(gx, g_gh[p], tid, hreg);
            sm->h[tid] = hreg;
        }
        __syncthreads();

        // ---- gh(t+1): 12 rows per block, weights in regs ----
        if (warp < 12) {
            float acc = 0.f;
            #pragma unroll
            for (int i = 0; i < 16; i++) acc += whh[i] * sm->h[lane + 32 * i];
            acc = wsum(acc);
            if (lane == 0) __stcg(&g_gh[q][b * 12 + warp], acc + bhh);
            __threadfence();
        }

        // ---- fused scores + z accumulation ----
        float zacc = 0.f;
        {
            #pragma unroll
            for (int rb = 0; rb < 8; rb += 4) {
                float a0 = 0.f, a1 = 0.f, a2v = 0.f, a3 = 0.f;
                #pragma unroll
                for (int c = 0; c < 2; c++) {
                    int ci = lane + 32 * c;
                    float4 ha = *(const float4*)&sm->h[ci * 8];
                    float4 hb = *(const float4*)&sm->h[ci * 8 + 4];
                    #pragma unroll
                    for (int rr = 0; rr < 4; rr++) {
                        int4 pk = ((const int4*)sm->keys[rbase + rb + rr])[ci];
                        float2 f0 = __half22float2(*(__half2*)&pk.x);
                        float2 f1 = __half22float2(*(__half2*)&pk.y);
                        float2 f2 = __half22float2(*(__half2*)&pk.z);
                        float2 f3 = __half22float2(*(__half2*)&pk.w);
                        float s = f0.x * ha.x + f0.y * ha.y + f1.x * ha.z + f1.y * ha.w
                                + f2.x * hb.x + f2.y * hb.y + f3.x * hb.z + f3.y * hb.w;
                        if (rr == 0) a0 += s; else if (rr == 1) a1 += s;
                        else if (rr == 2) a2v += s; else a3 += s;
                    }
                }
                #pragma unroll
                for (int o = 16; o; o >>= 1) {
                    a0  += __shfl_xor_sync(0xffffffffu, a0,  o);
                    a1  += __shfl_xor_sync(0xffffffffu, a1,  o);
                    a2v += __shfl_xor_sync(0xffffffffu, a2v, o);
                    a3  += __shfl_xor_sync(0xffffffffu, a3,  o);
                }
                #pragma unroll
                for (int rr = 0; rr < 4; rr++) {
                    int r = rbase + rb + rr;
                    float a = (rr == 0) ? a0 : (rr == 1) ? a1 : (rr == 2) ? a2v : a3;
                    float e = sm->maskb[r] * __expf(a * SCALE);
                    if (lane == rb + rr) sm->sc[r] = e;
                    zacc += e * pv[rb + rr];
                }
            }
            sm->zred[warp][lane] = zacc;
        }
        __syncthreads();

        // ---- publish partials + arrive ----
        if (warp == 0) {
            float s = 0.f;
            #pragma unroll
            for (int w = 0; w < NW; w++) s += sm->zred[w][lane];
            __stcg(&g_part[p][b][lane], s);
            __threadfence();
            if (lane == 0) atomicAdd(&g_arrive, 1);
        }

        // ---- a2[k] = w_out[k,512:].h + b_out[k] (shadow of the wait) ----
        for (int k = warp; k < VOCAB; k += NW) {
            float acc = 0.f;
            #pragma unroll
            for (int i = 0; i < 16; i++)
                acc += sm->wout_hi[k][lane + 32 * i] * sm->h[lane + 32 * i];
            acc = wsum(acc);
            if (lane == 0) sm->a2[k] = acc + b_out[k];
        }

        // ---- wait for all blocks of this step ----
        if (tid == 0) {
            int target = (t + 2) * NBW;
            while (*(volatile int*)&g_arrive < target) {}
            __threadfence();
        }
        __syncthreads();

        // ---- redundant combine: read all partials, logits, argmax ----
        {
            int k = tid & 31, grp = tid >> 5;
            float s = 0.f;
            #pragma unroll
            for (int i = 0; i < 8; i++)
                s += __ldcg(&g_part[p][grp * 8 + i][k]);
            sm->tot[grp][k] = s;
        }
        __syncthreads();
        if (tid < 32) {
            int k = tid;
            float s = 0.f;
            #pragma unroll
            for (int g = 0; g < 16; g++) s += sm->tot[g][k];
            float sg  = __shfl_sync(0xffffffffu, s, 31);
            float inv = __fdividef(1.f, sg);
            float lg  = (k < VOCAB) ? s * inv + sm->a2[k] : -3.4e38f;
            if (b == 0 && k < VOCAB) out[(size_t)t * VOCAB + k] = lg;
            float bv = lg; int bi = k;
            #pragma unroll
            for (int o = 16; o; o >>= 1) {
                float ov = __shfl_xor_sync(0xffffffffu, bv, o);
                int   oi = __shfl_xor_sync(0xffffffffu, bi, o);
                if (ov > bv || (ov == bv && oi < bi)) { bv = ov; bi = oi; }
            }
            if (k == 0) {
                sm->tok = bi;
                sm->inv = inv;
                if (b == 0) {
                    if (bi == EOS && len == STEPS) len = t;
                    if (t == STEPS - 1) out[OUT_LEN] = (float)len;
                }
            }
        }
        __syncthreads();

        // ---- attention output for this step (local inv) ----
        if (tid < CHUNK)
            out[OUT_ATT + (size_t)t * T_ENC + j0 + tid] = sm->sc[tid] * sm->inv;
    }

    // ================= teardown: reset counter for next replay =================
    __syncthreads();
    if (tid == 0) {
        __threadfence();
        atomicAdd(&g_arrive, 1);
        if (b == 0) {
            while (*(volatile int*)&g_arrive < (STEPS + 2) * NBW) {}
            atomicExch(&g_arrive, 0);
        }
    }
}

extern "C" void kernel_launch(void* const* d_in, const int* in_sizes, int n_in,
                              void* d_out, int out_size) {
    const float* enc    = (const float*)d_in[0];
    const float* embed  = (const float*)d_in[2];
    const float* w_ih   = (const float*)d_in[3];
    const float* w_hh   = (const float*)d_in[4];
    const float* b_ih   = (const float*)d_in[5];
    const float* b_hh   = (const float*)d_in[6];
    const float* w_out  = (const float*)d_in[7];
    const float* b_out  = (const float*)d_in[8];
    float* out = (float*)d_out;

    int smem = (int)sizeof(SMW);
    cudaFuncSetAttribute(decoder_kernel,
                         cudaFuncAttributeMaxDynamicSharedMemorySize, smem);
    decoder_kernel<<<NBW, NT, smem>>>(enc, embed, w_ih, w_hh, b_ih, b_hh,
                                      w_out, b_out, out);
}

// round 8
// speedup vs baseline: 4.8803x; 1.0098x over previous
#include <cuda_runtime.h>
#include <cuda_fp16.h>
#include <math.h>

#define T_ENC  16384
#define HID    512
#define G3     1536
#define VOCAB  31
#define STEPS  100
#define EOS    29
#define NBW    128
#define NT     512
#define NW     (NT/32)          // 16 warps
#define CHUNK  (T_ENC/NBW)      // 128 rows per block
#define SCALE  0.04419417382415922f

#define OUT_LEN (STEPS*VOCAB)
#define OUT_ATT (STEPS*VOCAB+1)

// ---------------- persistent device scratch ----------------
__device__ float4 g_gxp[HID * 32];       // packed {gxr,gxz,gxn,_} per (dim, token)
__device__ float  g_pv[T_ENC * 32];      // PV[j][k] = w_out[k,:512].v_j ; PV[j][31]=1
__device__ float  g_gh[2][G3];           // gh double-buffered by step parity
__device__ float  g_part[2][NBW][32];    // parity-buffered per-block partials
__device__ int    g_arrive = 0;          // single monotone arrival counter

// ---------------- smem layout (~197 KB) ----------------
struct __align__(16) SMW {
    uint2  keys[CHUNK][128];     // fp16 keys, 1 KB/row
    float  wout_hi[VOCAB][512];  // w_out[:, 512:]
    float  h[HID];
    float  sc[CHUNK];            // e = exp(score) (0 if masked)
    float  maskb[CHUNK];
    float  zred[NW][32];
    float  tot[NW][32];
    float  a2[32];
};

__device__ __forceinline__ float wsum(float v) {
    #pragma unroll
    for (int o = 16; o; o >>= 1) v += __shfl_xor_sync(0xffffffffu, v, o);
    return v;
}

// multi-issue spin: 4 independent loads in flight -> ~1 L2 RT detect latency
__device__ __forceinline__ void wait_target(int target) {
    const volatile int* ctr = &g_arrive;
    for (;;) {
        int v0 = *ctr; int v1 = *ctr; int v2 = *ctr; int v3 = *ctr;
        if (v0 >= target || v1 >= target || v2 >= target || v3 >= target) break;
    }
}

__global__ void __launch_bounds__(NT, 1)
decoder_kernel(const float* __restrict__ enc,
               const float* __restrict__ embed,
               const float* __restrict__ w_ih,
               const float* __restrict__ w_hh,
               const float* __restrict__ b_ih,
               const float* __restrict__ b_hh,
               const float* __restrict__ w_out,
               const float* __restrict__ b_out,
               float* __restrict__ out)
{
    extern __shared__ __align__(16) unsigned char smem_raw[];
    SMW* sm = (SMW*)smem_raw;

    const int tid  = threadIdx.x;
    const int b    = blockIdx.x;
    const int lane = tid & 31;
    const int warp = tid >> 5;
    const int j0   = b * CHUNK;
    const int rbase = warp * 8;

    float whh[16];
    float bhh = 0.f;

    // ================= setup =================
    // keys -> smem fp16, mask
    for (int r = warp; r < CHUNK; r += NW) {
        int j = j0 + r;
        const float4* src = (const float4*)(enc + (size_t)j * 1024);
        bool anyne = false;
        #pragma unroll
        for (int c = lane; c < 128; c += 32) {
            float4 f = src[c];
            anyne |= (f.x != 30.f) | (f.y != 30.f) | (f.z != 30.f) | (f.w != 30.f);
            __half2 a = __floats2half2_rn(f.x, f.y);
            __half2 bb = __floats2half2_rn(f.z, f.w);
            uint2 pk; pk.x = *(unsigned*)&a; pk.y = *(unsigned*)&bb;
            sm->keys[r][c] = pk;
        }
        bool msk = __any_sync(0xffffffffu, anyne);
        if (lane == 0) sm->maskb[r] = msk ? 1.f : 0.f;
    }
    // PV[j][k] = w_out[k,:512].v_j ; PV[j][31] = 1
    for (int pp = 0; pp < 4; pp++) {
        int r0 = j0 + rbase + pp * 2;
        float acc0[VOCAB], acc1[VOCAB];
        #pragma unroll
        for (int k = 0; k < VOCAB; k++) { acc0[k] = 0.f; acc1[k] = 0.f; }
        const float* v0p = enc + (size_t)r0 * 1024 + 512;
        const float* v1p = v0p + 1024;
        for (int d0 = 0; d0 < 512; d0 += 32) {
            float v0 = __ldg(v0p + d0 + lane);
            float v1 = __ldg(v1p + d0 + lane);
            #pragma unroll
            for (int k = 0; k < VOCAB; k++) {
                float w = __ldg(&w_out[(size_t)k * 1024 + d0 + lane]);
                acc0[k] += v0 * w;
                acc1[k] += v1 * w;
            }
        }
        #pragma unroll
        for (int k = 0; k < VOCAB; k++) {
            float s0 = wsum(acc0[k]);
            float s1 = wsum(acc1[k]);
            if (lane == 0) {
                g_pv[(size_t)r0 * 32 + k]       = s0;
                g_pv[(size_t)(r0 + 1) * 32 + k] = s1;
            }
        }
        if (lane == 0) {
            g_pv[(size_t)r0 * 32 + 31]       = 1.f;
            g_pv[(size_t)(r0 + 1) * 32 + 31] = 1.f;
        }
    }
    // w_out hi half -> smem
    for (int idx = tid; idx < VOCAB * 512; idx += NT) {
        int k = idx >> 9, d = idx & 511;
        sm->wout_hi[k][d] = w_out[(size_t)k * 1024 + 512 + d];
    }
    // w_hh rows -> regs (warp w<12 owns row b*12+w)
    if (warp < 12) {
        int o = b * 12 + warp;
        const float* wr = w_hh + (size_t)o * HID;
        #pragma unroll
        for (int i = 0; i < 16; i++) whh[i] = wr[lane + 32 * i];
        bhh = b_hh[o];
    }
    // gx table portion -> packed layout g_gxp[d][tok] = {gxr,gxz,gxn,_}
    {
        int wg = b * NW + warp;
        for (int r = wg; r < G3; r += NBW * NW) {
            const float* wr = w_ih + (size_t)r * HID;
            float wreg[16];
            #pragma unroll
            for (int i = 0; i < 16; i++) wreg[i] = wr[lane + 32 * i];
            float bias = b_ih[r];
            int gate = r >> 9, d = r & 511;
            for (int v = 0; v < VOCAB; v++) {
                const float* er = embed + (size_t)v * HID;
                float acc = 0.f;
                #pragma unroll
                for (int i = 0; i < 16; i++) acc += wreg[i] * er[lane + 32 * i];
                acc = wsum(acc);
                if (lane == 0)
                    ((float*)g_gxp)[((size_t)(d * 32 + v)) * 4 + gate] = acc + bias;
            }
        }
    }
    // gh[0] = b_hh (h0 = 0): block 0 writes it
    if (b == 0)
        for (int i = tid; i < G3; i += NT) __stcg(&g_gh[0][i], b_hh[i]);
    __syncthreads();
    // initial barrier
    if (tid == 0) {
        __threadfence();
        atomicAdd(&g_arrive, 1);
        wait_target(NBW);
        __threadfence();
    }
    __syncthreads();

    // PV registers (step-invariant)
    float pv[8];
    #pragma unroll
    for (int r = 0; r < 8; r++)
        pv[r] = __ldcg(&g_pv[(size_t)(j0 + rbase + r) * 32 + lane]);

    // prefetch gh for step 0
    float ghr = __ldcg(&g_gh[0][tid]);
    float ghz = __ldcg(&g_gh[0][HID + tid]);
    float ghn = __ldcg(&g_gh[0][2 * HID + tid]);

    // ================= decode loop =================
    float hreg = 0.f;
    float av = 0.f, invreg = 0.f;
    int   tok = EOS;
    int   len = STEPS;

    for (int t = 0; t < STEPS; t++) {
        const int p = t & 1, q = p ^ 1;

        // ---- GRU: one packed gx load, gh already in regs ----
        {
            float4 gx4 = __ldcg(&g_gxp[tid * 32 + tok]);
            float xr = gx4.x + ghr;
            float xz = gx4.y + ghz;
            float r_ = __fdividef(1.f, 1.f + __expf(-xr));
            float z_ = __fdividef(1.f, 1.f + __expf(-xz));
            float nx = gx4.z + r_ * ghn;
            nx = fminf(fmaxf(nx, -15.f), 15.f);
            float t2 = __expf(2.f * nx);
            float n_ = __fdividef(t2 - 1.f, t2 + 1.f);
            hreg = (1.f - z_) * n_ + z_ * hreg;
            sm->h[tid] = hreg;
        }
        __syncthreads();

        // ---- gh(t+1): 12 rows per block, weights in regs ----
        if (warp < 12) {
            float acc = 0.f;
            #pragma unroll
            for (int i = 0; i < 16; i++) acc += whh[i] * sm->h[lane + 32 * i];
            acc = wsum(acc);
            if (lane == 0) __stcg(&g_gh[q][b * 12 + warp], acc + bhh);
        }

        // ---- fused scores + z accumulation ----
        float zacc = 0.f;
        {
            #pragma unroll
            for (int rb = 0; rb < 8; rb += 4) {
                float a0 = 0.f, a1 = 0.f, a2v = 0.f, a3 = 0.f;
                #pragma unroll
                for (int c = 0; c < 2; c++) {
                    int ci = lane + 32 * c;
                    float4 ha = *(const float4*)&sm->h[ci * 8];
                    float4 hb = *(const float4*)&sm->h[ci * 8 + 4];
                    #pragma unroll
                    for (int rr = 0; rr < 4; rr++) {
                        int4 pk = ((const int4*)sm->keys[rbase + rb + rr])[ci];
                        float2 f0 = __half22float2(*(__half2*)&pk.x);
                        float2 f1 = __half22float2(*(__half2*)&pk.y);
                        float2 f2 = __half22float2(*(__half2*)&pk.z);
                        float2 f3 = __half22float2(*(__half2*)&pk.w);
                        float s = f0.x * ha.x + f0.y * ha.y + f1.x * ha.z + f1.y * ha.w
                                + f2.x * hb.x + f2.y * hb.y + f3.x * hb.z + f3.y * hb.w;
                        if (rr == 0) a0 += s; else if (rr == 1) a1 += s;
                        else if (rr == 2) a2v += s; else a3 += s;
                    }
                }
                #pragma unroll
                for (int o = 16; o; o >>= 1) {
                    a0  += __shfl_xor_sync(0xffffffffu, a0,  o);
                    a1  += __shfl_xor_sync(0xffffffffu, a1,  o);
                    a2v += __shfl_xor_sync(0xffffffffu, a2v, o);
                    a3  += __shfl_xor_sync(0xffffffffu, a3,  o);
                }
                #pragma unroll
                for (int rr = 0; rr < 4; rr++) {
                    int r = rbase + rb + rr;
                    float a = (rr == 0) ? a0 : (rr == 1) ? a1 : (rr == 2) ? a2v : a3;
                    float e = sm->maskb[r] * __expf(a * SCALE);
                    if (lane == rb + rr) sm->sc[r] = e;
                    zacc += e * pv[rb + rr];
                }
            }
            sm->zred[warp][lane] = zacc;
        }
        __syncthreads();

        // ---- publish partials + arrive (warp 0) ----
        if (warp == 0) {
            float s = 0.f;
            #pragma unroll
            for (int w = 0; w < NW; w++) s += sm->zred[w][lane];
            __stcg(&g_part[p][b][lane], s);
            __threadfence();
            if (lane == 0) atomicAdd(&g_arrive, 1);
        }

        // ---- shadow: a2, deferred attn write, capture this step's e ----
        for (int k = warp; k < VOCAB; k += NW) {
            float acc = 0.f;
            #pragma unroll
            for (int i = 0; i < 16; i++)
                acc += sm->wout_hi[k][lane + 32 * i] * sm->h[lane + 32 * i];
            acc = wsum(acc);
            if (lane == 0) sm->a2[k] = acc + b_out[k];
        }
        if (tid < CHUNK) {
            if (t > 0)
                out[OUT_ATT + (size_t)(t - 1) * T_ENC + j0 + tid] = av * invreg;
            av = sm->sc[tid];
        }

        // ---- wait for all blocks ----
        if (tid == 0) {
            wait_target((t + 2) * NBW);
            __threadfence();
        }
        __syncthreads();

        // ---- prefetch next gh (hides under combine) ----
        float ghr_n = __ldcg(&g_gh[q][tid]);
        float ghz_n = __ldcg(&g_gh[q][HID + tid]);
        float ghn_n = __ldcg(&g_gh[q][2 * HID + tid]);

        // ---- redundant combine (every warp -> tok/inv in regs) ----
        {
            float s = 0.f;
            #pragma unroll
            for (int i = 0; i < 8; i++)
                s += __ldcg(&g_part[p][warp * 8 + i][lane]);
            sm->tot[warp][lane] = s;
        }
        __syncthreads();
        {
            float s = 0.f;
            #pragma unroll
            for (int g = 0; g < NW; g++) s += sm->tot[g][lane];
            float sg  = __shfl_sync(0xffffffffu, s, 31);
            float inv = __fdividef(1.f, sg);
            invreg = inv;
            float lg  = (lane < VOCAB) ? s * inv + sm->a2[lane] : -3.4e38f;
            float bv = lg; int bi = lane;
            #pragma unroll
            for (int o = 16; o; o >>= 1) {
                float ov = __shfl_xor_sync(0xffffffffu, bv, o);
                int   oi = __shfl_xor_sync(0xffffffffu, bi, o);
                if (ov > bv || (ov == bv && oi < bi)) { bv = ov; bi = oi; }
            }
            tok = bi;                       // identical in every warp/block
            if (b == 0 && warp == 0) {
                if (lane < VOCAB) out[(size_t)t * VOCAB + lane] = lg;
                if (lane == 0) {
                    if (bi == EOS && len == STEPS) len = t;
                }
            }
        }
        ghr = ghr_n; ghz = ghz_n; ghn = ghn_n;
    }

    // final attention row + length
    if (tid < CHUNK)
        out[OUT_ATT + (size_t)(STEPS - 1) * T_ENC + j0 + tid] = av * invreg;
    if (b == 0 && warp == 0 && lane == 0) out[OUT_LEN] = (float)len;

    // ================= teardown: reset counter for next replay =================
    __syncthreads();
    if (tid == 0) {
        __threadfence();
        atomicAdd(&g_arrive, 1);
        if (b == 0) {
            wait_target((STEPS + 2) * NBW);
            atomicExch(&g_arrive, 0);
        }
    }
}

extern "C" void kernel_launch(void* const* d_in, const int* in_sizes, int n_in,
                              void* d_out, int out_size) {
    const float* enc    = (const float*)d_in[0];
    const float* embed  = (const float*)d_in[2];
    const float* w_ih   = (const float*)d_in[3];
    const float* w_hh   = (const float*)d_in[4];
    const float* b_ih   = (const float*)d_in[5];
    const float* b_hh   = (const float*)d_in[6];
    const float* w_out  = (const float*)d_in[7];
    const float* b_out  = (const float*)d_in[8];
    float* out = (float*)d_out;

    int smem = (int)sizeof(SMW);
    cudaFuncSetAttribute(decoder_kernel,
                         cudaFuncAttributeMaxDynamicSharedMemorySize, smem);
    decoder_kernel<<<NBW, NT, smem>>>(enc, embed, w_ih, w_hh, b_ih, b_hh,
                                      w_out, b_out, out);
}

// round 12
// speedup vs baseline: 5.4915x; 1.1252x over previous
#include <cuda_runtime.h>
#include <cuda_fp16.h>
#include <math.h>

#define T_ENC  16384
#define HID    512
#define G3     1536
#define VOCAB  31
#define STEPS  100
#define EOS    29
#define NBW    128
#define NT     512
#define NW     (NT/32)          // 16 warps
#define CHUNK  (T_ENC/NBW)      // 128 rows per block
#define SCALE  0.04419417382415922f

#define OUT_LEN (STEPS*VOCAB)
#define OUT_ATT (STEPS*VOCAB+1)

// ---------------- persistent device scratch ----------------
__device__ float4 g_gx2[VOCAB * HID];    // [tok][dim] packed {gxr,gxz,gxn,_} — coalesced
__device__ float  g_pv[T_ENC * 32];      // PV[j][k] = w_out[k,:512].v_j ; PV[j][31]=1
__device__ float  g_gh[2][G3];           // gh double-buffered by step parity
__device__ float  g_part[2][NBW][32];    // parity-buffered per-block partials
__device__ int    g_arrive = 0;          // single monotone arrival counter

// ---------------- smem layout (~199 KB) ----------------
struct __align__(16) SMW {
    uint2   keys[CHUNK][128];     // fp16 keys, 1 KB/row
    float   wout_hi[VOCAB][512];  // w_out[:, 512:]
    float   h[HID];               // fp32 h (for gh / a2)
    __half2 h2[HID / 2];          // fp16 h (for scores)
    float   sc[CHUNK];            // e = exp(score) (0 if masked)
    float   maskb[CHUNK];
    float   zred[NW][32];
    float   tot[NW][32];
    float   a2[32];
};

__device__ __forceinline__ float wsum(float v) {
    #pragma unroll
    for (int o = 16; o; o >>= 1) v += __shfl_xor_sync(0xffffffffu, v, o);
    return v;
}

// multi-issue spin: 4 independent loads in flight -> ~1 L2 RT detect latency
__device__ __forceinline__ void wait_target(int target) {
    const volatile int* ctr = &g_arrive;
    for (;;) {
        int v0 = *ctr; int v1 = *ctr; int v2 = *ctr; int v3 = *ctr;
        if (v0 >= target || v1 >= target || v2 >= target || v3 >= target) break;
    }
}

__global__ void __launch_bounds__(NT, 1)
decoder_kernel(const float* __restrict__ enc,
               const float* __restrict__ embed,
               const float* __restrict__ w_ih,
               const float* __restrict__ w_hh,
               const float* __restrict__ b_ih,
               const float* __restrict__ b_hh,
               const float* __restrict__ w_out,
               const float* __restrict__ b_out,
               float* __restrict__ out)
{
    extern __shared__ __align__(16) unsigned char smem_raw[];
    SMW* sm = (SMW*)smem_raw;

    const int tid  = threadIdx.x;
    const int b    = blockIdx.x;
    const int lane = tid & 31;
    const int warp = tid >> 5;
    const int j0   = b * CHUNK;
    const int rbase = warp * 8;

    float whh[16];
    float bhh = 0.f;

    // ================= setup =================
    // keys -> smem fp16, mask
    for (int r = warp; r < CHUNK; r += NW) {
        int j = j0 + r;
        const float4* src = (const float4*)(enc + (size_t)j * 1024);
        bool anyne = false;
        #pragma unroll
        for (int c = lane; c < 128; c += 32) {
            float4 f = src[c];
            anyne |= (f.x != 30.f) | (f.y != 30.f) | (f.z != 30.f) | (f.w != 30.f);
            __half2 a = __floats2half2_rn(f.x, f.y);
            __half2 bb = __floats2half2_rn(f.z, f.w);
            uint2 pk; pk.x = *(unsigned*)&a; pk.y = *(unsigned*)&bb;
            sm->keys[r][c] = pk;
        }
        bool msk = __any_sync(0xffffffffu, anyne);
        if (lane == 0) sm->maskb[r] = msk ? 1.f : 0.f;
    }
    // PV[j][k] = w_out[k,:512].v_j ; PV[j][31] = 1
    for (int pp = 0; pp < 4; pp++) {
        int r0 = j0 + rbase + pp * 2;
        float acc0[VOCAB], acc1[VOCAB];
        #pragma unroll
        for (int k = 0; k < VOCAB; k++) { acc0[k] = 0.f; acc1[k] = 0.f; }
        const float* v0p = enc + (size_t)r0 * 1024 + 512;
        const float* v1p = v0p + 1024;
        for (int d0 = 0; d0 < 512; d0 += 32) {
            float v0 = __ldg(v0p + d0 + lane);
            float v1 = __ldg(v1p + d0 + lane);
            #pragma unroll
            for (int k = 0; k < VOCAB; k++) {
                float w = __ldg(&w_out[(size_t)k * 1024 + d0 + lane]);
                acc0[k] += v0 * w;
                acc1[k] += v1 * w;
            }
        }
        #pragma unroll
        for (int k = 0; k < VOCAB; k++) {
            float s0 = wsum(acc0[k]);
            float s1 = wsum(acc1[k]);
            if (lane == 0) {
                g_pv[(size_t)r0 * 32 + k]       = s0;
                g_pv[(size_t)(r0 + 1) * 32 + k] = s1;
            }
        }
        if (lane == 0) {
            g_pv[(size_t)r0 * 32 + 31]       = 1.f;
            g_pv[(size_t)(r0 + 1) * 32 + 31] = 1.f;
        }
    }
    // w_out hi half -> smem
    for (int idx = tid; idx < VOCAB * 512; idx += NT) {
        int k = idx >> 9, d = idx & 511;
        sm->wout_hi[k][d] = w_out[(size_t)k * 1024 + 512 + d];
    }
    // w_hh rows -> regs (warp w<12 owns row b*12+w)
    if (warp < 12) {
        int o = b * 12 + warp;
        const float* wr = w_hh + (size_t)o * HID;
        #pragma unroll
        for (int i = 0; i < 16; i++) whh[i] = wr[lane + 32 * i];
        bhh = b_hh[o];
    }
    // gx table portion -> coalesced layout g_gx2[tok*512 + d] = {gxr,gxz,gxn,_}
    {
        int wg = b * NW + warp;
        for (int r = wg; r < G3; r += NBW * NW) {
            const float* wr = w_ih + (size_t)r * HID;
            float wreg[16];
            #pragma unroll
            for (int i = 0; i < 16; i++) wreg[i] = wr[lane + 32 * i];
            float bias = b_ih[r];
            int gate = r >> 9, d = r & 511;
            for (int v = 0; v < VOCAB; v++) {
                const float* er = embed + (size_t)v * HID;
                float acc = 0.f;
                #pragma unroll
                for (int i = 0; i < 16; i++) acc += wreg[i] * er[lane + 32 * i];
                acc = wsum(acc);
                if (lane == 0)
                    ((float*)g_gx2)[((size_t)v * HID + d) * 4 + gate] = acc + bias;
            }
        }
    }
    // gh[0] = b_hh (h0 = 0): block 0 writes it
    if (b == 0)
        for (int i = tid; i < G3; i += NT) __stcg(&g_gh[0][i], b_hh[i]);
    __syncthreads();
    // initial barrier
    if (tid == 0) {
        __threadfence();
        atomicAdd(&g_arrive, 1);
        wait_target(NBW);
        __threadfence();
    }
    __syncthreads();

    // step-invariant registers
    float pv[8], mreg[8];
    #pragma unroll
    for (int r = 0; r < 8; r++) {
        pv[r]   = __ldcg(&g_pv[(size_t)(j0 + rbase + r) * 32 + lane]);
        mreg[r] = sm->maskb[rbase + r];
    }

    // prefetch gh for step 0
    float ghr = __ldcg(&g_gh[0][tid]);
    float ghz = __ldcg(&g_gh[0][HID + tid]);
    float ghn = __ldcg(&g_gh[0][2 * HID + tid]);

    // ================= decode loop =================
    float hreg = 0.f;
    float av = 0.f, invreg = 0.f;
    int   tok = EOS;
    int   len = STEPS;

    for (int t = 0; t < STEPS; t++) {
        const int p = t & 1, q = p ^ 1;

        // ---- GRU: coalesced packed gx load, gh in regs ----
        {
            float4 gx4 = __ldcg(&g_gx2[tok * HID + tid]);
            float xr = gx4.x + ghr;
            float xz = gx4.y + ghz;
            float r_ = __fdividef(1.f, 1.f + __expf(-xr));
            float z_ = __fdividef(1.f, 1.f + __expf(-xz));
            float nx = gx4.z + r_ * ghn;
            nx = fminf(fmaxf(nx, -15.f), 15.f);
            float t2 = __expf(2.f * nx);
            float n_ = __fdividef(t2 - 1.f, t2 + 1.f);
            hreg = (1.f - z_) * n_ + z_ * hreg;
            sm->h[tid] = hreg;
            // fp16 mirror: even threads pack (h[tid], h[tid+1])
            float hn = __shfl_down_sync(0xffffffffu, hreg, 1);
            if ((tid & 1) == 0) sm->h2[tid >> 1] = __floats2half2_rn(hreg, hn);
        }
        __syncthreads();

        // ---- gh(t+1): 12 rows per block, weights in regs ----
        if (warp < 12) {
            float acc = 0.f;
            #pragma unroll
            for (int i = 0; i < 16; i++) acc += whh[i] * sm->h[lane + 32 * i];
            acc = wsum(acc);
            if (lane == 0) __stcg(&g_gh[q][b * 12 + warp], acc + bhh);
        }

        // ---- fused fp16 scores + z accumulation (8 rows per warp) ----
        float zacc = 0.f;
        {
            float acc[8];
            #pragma unroll
            for (int r = 0; r < 8; r++) acc[r] = 0.f;
            #pragma unroll
            for (int c = 0; c < 2; c++) {
                int ci = lane + 32 * c;
                uint4 h4 = ((const uint4*)sm->h2)[ci];
                __half2 hh0 = *(__half2*)&h4.x;
                __half2 hh1 = *(__half2*)&h4.y;
                __half2 hh2 = *(__half2*)&h4.z;
                __half2 hh3 = *(__half2*)&h4.w;
                #pragma unroll
                for (int r = 0; r < 8; r++) {
                    int4 pk = ((const int4*)sm->keys[rbase + r])[ci];
                    __half2 k0 = *(__half2*)&pk.x;
                    __half2 k1 = *(__half2*)&pk.y;
                    __half2 k2 = *(__half2*)&pk.z;
                    __half2 k3 = *(__half2*)&pk.w;
                    __half2 a2h = __hmul2(k0, hh0);
                    a2h = __hfma2(k1, hh1, a2h);
                    a2h = __hfma2(k2, hh2, a2h);
                    a2h = __hfma2(k3, hh3, a2h);
                    float2 f = __half22float2(a2h);
                    acc[r] += f.x + f.y;
                }
            }
            // batched butterfly: 8 independent reduction chains
            #pragma unroll
            for (int o = 16; o; o >>= 1) {
                #pragma unroll
                for (int r = 0; r < 8; r++)
                    acc[r] += __shfl_xor_sync(0xffffffffu, acc[r], o);
            }
            #pragma unroll
            for (int r = 0; r < 8; r++) {
                float e = mreg[r] * __expf(acc[r] * SCALE);
                if (lane == r) sm->sc[rbase + r] = e;
                zacc += e * pv[r];
            }
            sm->zred[warp][lane] = zacc;
        }
        __syncthreads();

        // ---- publish partials + arrive (warp 0) ----
        if (warp == 0) {
            float s = 0.f;
            #pragma unroll
            for (int w = 0; w < NW; w++) s += sm->zred[w][lane];
            __stcg(&g_part[p][b][lane], s);
            __threadfence();
            if (lane == 0) atomicAdd(&g_arrive, 1);
        }

        // ---- shadow: a2, deferred attn write, capture this step's e ----
        for (int k = warp; k < VOCAB; k += NW) {
            float acc = 0.f;
            #pragma unroll
            for (int i = 0; i < 16; i++)
                acc += sm->wout_hi[k][lane + 32 * i] * sm->h[lane + 32 * i];
            acc = wsum(acc);
            if (lane == 0) sm->a2[k] = acc + b_out[k];
        }
        if (tid < CHUNK) {
            if (t > 0)
                out[OUT_ATT + (size_t)(t - 1) * T_ENC + j0 + tid] = av * invreg;
            av = sm->sc[tid];
        }

        // ---- wait for all blocks ----
        if (tid == 0) {
            wait_target((t + 2) * NBW);
            __threadfence();
        }
        __syncthreads();

        // ---- prefetch next gh (hides under combine) ----
        float ghr_n = __ldcg(&g_gh[q][tid]);
        float ghz_n = __ldcg(&g_gh[q][HID + tid]);
        float ghn_n = __ldcg(&g_gh[q][2 * HID + tid]);

        // ---- redundant combine (every warp -> tok/inv in regs) ----
        {
            float s = 0.f;
            #pragma unroll
            for (int i = 0; i < 8; i++)
                s += __ldcg(&g_part[p][warp * 8 + i][lane]);
            sm->tot[warp][lane] = s;
        }
        __syncthreads();
        {
            float s = 0.f;
            #pragma unroll
            for (int g = 0; g < NW; g++) s += sm->tot[g][lane];
            float sg  = __shfl_sync(0xffffffffu, s, 31);
            float inv = __fdividef(1.f, sg);
            invreg = inv;
            float lg  = (lane < VOCAB) ? s * inv + sm->a2[lane] : -3.4e38f;
            float bv = lg; int bi = lane;
            #pragma unroll
            for (int o = 16; o; o >>= 1) {
                float ov = __shfl_xor_sync(0xffffffffu, bv, o);
                int   oi = __shfl_xor_sync(0xffffffffu, bi, o);
                if (ov > bv || (ov == bv && oi < bi)) { bv = ov; bi = oi; }
            }
            tok = bi;                       // identical in every warp/block
            if (b == 0 && warp == 0) {
                if (lane < VOCAB) out[(size_t)t * VOCAB + lane] = lg;
                if (lane == 0) {
                    if (bi == EOS && len == STEPS) len = t;
                }
            }
        }
        ghr = ghr_n; ghz = ghz_n; ghn = ghn_n;
    }

    // final attention row + length
    if (tid < CHUNK)
        out[OUT_ATT + (size_t)(STEPS - 1) * T_ENC + j0 + tid] = av * invreg;
    if (b == 0 && warp == 0 && lane == 0) out[OUT_LEN] = (float)len;

    // ================= teardown: reset counter for next replay =================
    __syncthreads();
    if (tid == 0) {
        __threadfence();
        atomicAdd(&g_arrive, 1);
        if (b == 0) {
            wait_target((STEPS + 2) * NBW);
            atomicExch(&g_arrive, 0);
        }
    }
}

extern "C" void kernel_launch(void* const* d_in, const int* in_sizes, int n_in,
                              void* d_out, int out_size) {
    const float* enc    = (const float*)d_in[0];
    const float* embed  = (const float*)d_in[2];
    const float* w_ih   = (const float*)d_in[3];
    const float* w_hh   = (const float*)d_in[4];
    const float* b_ih   = (const float*)d_in[5];
    const float* b_hh   = (const float*)d_in[6];
    const float* w_out  = (const float*)d_in[7];
    const float* b_out  = (const float*)d_in[8];
    float* out = (float*)d_out;

    int smem = (int)sizeof(SMW);
    cudaFuncSetAttribute(decoder_kernel,
                         cudaFuncAttributeMaxDynamicSharedMemorySize, smem);
    decoder_kernel<<<NBW, NT, smem>>>(enc, embed, w_ih, w_hh, b_ih, b_hh,
                                      w_out, b_out, out);
}

// round 15
// speedup vs baseline: 5.4926x; 1.0002x over previous
#include <cuda_runtime.h>
#include <cuda_fp16.h>
#include <math.h>

#define T_ENC  16384
#define HID    512
#define G3     1536
#define VOCAB  31
#define STEPS  100
#define EOS    29
#define NBW    128
#define NT     512
#define NW     (NT/32)          // 16 warps
#define CHUNK  (T_ENC/NBW)      // 128 rows per block
#define SCALE  0.04419417382415922f

#define OUT_LEN (STEPS*VOCAB)
#define OUT_ATT (STEPS*VOCAB+1)

// ---------------- persistent device scratch ----------------
__device__ float4 g_gx2[VOCAB * HID];    // [tok][dim] packed {gxr,gxz,gxn,_}
__device__ float  g_pv[T_ENC * 32];      // PV[j][k] = w_out[k,:512].v_j ; PV[j][31]=1
__device__ float  g_gh[2][G3];           // gh double-buffered by step parity
__device__ float  g_part[2][NBW][32];    // parity-buffered per-block partials
__device__ int    g_flag[NBW];           // per-block monotone publish flags
__device__ int    g_arrive = 0;          // teardown-only rendezvous

// ---------------- smem layout (~199 KB) ----------------
struct __align__(16) SMW {
    uint2   keys[CHUNK][128];     // fp16 keys, 1 KB/row
    float   wout_hi[VOCAB][512];  // w_out[:, 512:]
    float   h[HID];               // fp32 h (for gh / a2)
    __half2 h2[HID / 2];          // fp16 h (for scores)
    float   sc[CHUNK];            // e = exp(score) (0 if masked)
    float   maskb[CHUNK];
    float   zred[NW][32];
    float   tot[NW][32];
    float   a2[32];
};

__device__ __forceinline__ float wsum(float v) {
    #pragma unroll
    for (int o = 16; o; o >>= 1) v += __shfl_xor_sync(0xffffffffu, v, o);
    return v;
}

// per-thread multi-issue poll on one flag word
__device__ __forceinline__ void poll_flag(const int* p, int target) {
    const volatile int* f = (const volatile int*)p;
    for (;;) {
        int v0 = *f; int v1 = *f; int v2 = *f; int v3 = *f;
        if (v0 >= target || v1 >= target || v2 >= target || v3 >= target) break;
    }
}

__global__ void __launch_bounds__(NT, 1)
decoder_kernel(const float* __restrict__ enc,
               const float* __restrict__ embed,
               const float* __restrict__ w_ih,
               const float* __restrict__ w_hh,
               const float* __restrict__ b_ih,
               const float* __restrict__ b_hh,
               const float* __restrict__ w_out,
               const float* __restrict__ b_out,
               float* __restrict__ out)
{
    extern __shared__ __align__(16) unsigned char smem_raw[];
    SMW* sm = (SMW*)smem_raw;

    const int tid  = threadIdx.x;
    const int b    = blockIdx.x;
    const int lane = tid & 31;
    const int warp = tid >> 5;
    const int j0   = b * CHUNK;
    const int rbase = warp * 8;

    float whh[16];
    float bhh = 0.f;

    // ================= setup =================
    // keys -> smem fp16, mask
    for (int r = warp; r < CHUNK; r += NW) {
        int j = j0 + r;
        const float4* src = (const float4*)(enc + (size_t)j * 1024);
        bool anyne = false;
        #pragma unroll
        for (int c = lane; c < 128; c += 32) {
            float4 f = src[c];
            anyne |= (f.x != 30.f) | (f.y != 30.f) | (f.z != 30.f) | (f.w != 30.f);
            __half2 a = __floats2half2_rn(f.x, f.y);
            __half2 bb = __floats2half2_rn(f.z, f.w);
            uint2 pk; pk.x = *(unsigned*)&a; pk.y = *(unsigned*)&bb;
            sm->keys[r][c] = pk;
        }
        bool msk = __any_sync(0xffffffffu, anyne);
        if (lane == 0) sm->maskb[r] = msk ? 1.f : 0.f;
    }
    // PV[j][k] = w_out[k,:512].v_j ; PV[j][31] = 1
    for (int pp = 0; pp < 4; pp++) {
        int r0 = j0 + rbase + pp * 2;
        float acc0[VOCAB], acc1[VOCAB];
        #pragma unroll
        for (int k = 0; k < VOCAB; k++) { acc0[k] = 0.f; acc1[k] = 0.f; }
        const float* v0p = enc + (size_t)r0 * 1024 + 512;
        const float* v1p = v0p + 1024;
        for (int d0 = 0; d0 < 512; d0 += 32) {
            float v0 = __ldg(v0p + d0 + lane);
            float v1 = __ldg(v1p + d0 + lane);
            #pragma unroll
            for (int k = 0; k < VOCAB; k++) {
                float w = __ldg(&w_out[(size_t)k * 1024 + d0 + lane]);
                acc0[k] += v0 * w;
                acc1[k] += v1 * w;
            }
        }
        #pragma unroll
        for (int k = 0; k < VOCAB; k++) {
            float s0 = wsum(acc0[k]);
            float s1 = wsum(acc1[k]);
            if (lane == 0) {
                g_pv[(size_t)r0 * 32 + k]       = s0;
                g_pv[(size_t)(r0 + 1) * 32 + k] = s1;
            }
        }
        if (lane == 0) {
            g_pv[(size_t)r0 * 32 + 31]       = 1.f;
            g_pv[(size_t)(r0 + 1) * 32 + 31] = 1.f;
        }
    }
    // w_out hi half -> smem
    for (int idx = tid; idx < VOCAB * 512; idx += NT) {
        int k = idx >> 9, d = idx & 511;
        sm->wout_hi[k][d] = w_out[(size_t)k * 1024 + 512 + d];
    }
    // w_hh rows -> regs (warp w<12 owns row b*12+w)
    if (warp < 12) {
        int o = b * 12 + warp;
        const float* wr = w_hh + (size_t)o * HID;
        #pragma unroll
        for (int i = 0; i < 16; i++) whh[i] = wr[lane + 32 * i];
        bhh = b_hh[o];
    }
    // gx table portion -> coalesced layout g_gx2[tok*512 + d] = {gxr,gxz,gxn,_}
    {
        int wg = b * NW + warp;
        for (int r = wg; r < G3; r += NBW * NW) {
            const float* wr = w_ih + (size_t)r * HID;
            float wreg[16];
            #pragma unroll
            for (int i = 0; i < 16; i++) wreg[i] = wr[lane + 32 * i];
            float bias = b_ih[r];
            int gate = r >> 9, d = r & 511;
            for (int v = 0; v < VOCAB; v++) {
                const float* er = embed + (size_t)v * HID;
                float acc = 0.f;
                #pragma unroll
                for (int i = 0; i < 16; i++) acc += wreg[i] * er[lane + 32 * i];
                acc = wsum(acc);
                if (lane == 0)
                    ((float*)g_gx2)[((size_t)v * HID + d) * 4 + gate] = acc + bias;
            }
        }
    }
    // gh[0] = b_hh (h0 = 0): block 0 writes it
    if (b == 0)
        for (int i = tid; i < G3; i += NT) __stcg(&g_gh[0][i], b_hh[i]);
    __syncthreads();
    // setup barrier: publish flag=1, poll all flags (one per thread)
    if (tid == 0) { __threadfence(); __stcg(&g_flag[b], 1); }
    if (tid < NBW) {
        poll_flag(&g_flag[tid], 1);
        __threadfence();
    }
    __syncthreads();

    // step-invariant registers
    float pv[8], mreg[8];
    #pragma unroll
    for (int r = 0; r < 8; r++) {
        pv[r]   = __ldcg(&g_pv[(size_t)(j0 + rbase + r) * 32 + lane]);
        mreg[r] = sm->maskb[rbase + r];
    }

    // prefetch gh for step 0
    float ghr = __ldcg(&g_gh[0][tid]);
    float ghz = __ldcg(&g_gh[0][HID + tid]);
    float ghn = __ldcg(&g_gh[0][2 * HID + tid]);

    // ================= decode loop =================
    float hreg = 0.f;
    float av = 0.f, invreg = 0.f;
    int   tok = EOS;
    int   len = STEPS;

    for (int t = 0; t < STEPS; t++) {
        const int p = t & 1, q = p ^ 1;

        // ---- GRU: gx via L1-cached load (immutable; token rows repeat) ----
        {
            float4 gx4 = __ldg(&g_gx2[tok * HID + tid]);
            float xr = gx4.x + ghr;
            float xz = gx4.y + ghz;
            float r_ = __fdividef(1.f, 1.f + __expf(-xr));
            float z_ = __fdividef(1.f, 1.f + __expf(-xz));
            float nx = gx4.z + r_ * ghn;
            nx = fminf(fmaxf(nx, -15.f), 15.f);
            float t2 = __expf(2.f * nx);
            float n_ = __fdividef(t2 - 1.f, t2 + 1.f);
            hreg = (1.f - z_) * n_ + z_ * hreg;
            sm->h[tid] = hreg;
            // fp16 mirror: even threads pack (h[tid], h[tid+1])
            float hn = __shfl_down_sync(0xffffffffu, hreg, 1);
            if ((tid & 1) == 0) sm->h2[tid >> 1] = __floats2half2_rn(hreg, hn);
        }
        __syncthreads();

        // ---- gh(t+1): 12 rows per block, weights in regs ----
        if (warp < 12) {
            float acc = 0.f;
            #pragma unroll
            for (int i = 0; i < 16; i++) acc += whh[i] * sm->h[lane + 32 * i];
            acc = wsum(acc);
            if (lane == 0) __stcg(&g_gh[q][b * 12 + warp], acc + bhh);
        }

        // ---- fused fp16 scores + z accumulation (8 rows per warp) ----
        float zacc = 0.f;
        {
            float acc[8];
            #pragma unroll
            for (int r = 0; r < 8; r++) acc[r] = 0.f;
            #pragma unroll
            for (int c = 0; c < 2; c++) {
                int ci = lane + 32 * c;
                uint4 h4 = ((const uint4*)sm->h2)[ci];
                __half2 hh0 = *(__half2*)&h4.x;
                __half2 hh1 = *(__half2*)&h4.y;
                __half2 hh2 = *(__half2*)&h4.z;
                __half2 hh3 = *(__half2*)&h4.w;
                #pragma unroll
                for (int r = 0; r < 8; r++) {
                    int4 pk = ((const int4*)sm->keys[rbase + r])[ci];
                    __half2 k0 = *(__half2*)&pk.x;
                    __half2 k1 = *(__half2*)&pk.y;
                    __half2 k2 = *(__half2*)&pk.z;
                    __half2 k3 = *(__half2*)&pk.w;
                    __half2 a2h = __hmul2(k0, hh0);
                    a2h = __hfma2(k1, hh1, a2h);
                    a2h = __hfma2(k2, hh2, a2h);
                    a2h = __hfma2(k3, hh3, a2h);
                    float2 f = __half22float2(a2h);
                    acc[r] += f.x + f.y;
                }
            }
            // batched butterfly: 8 independent reduction chains
            #pragma unroll
            for (int o = 16; o; o >>= 1) {
                #pragma unroll
                for (int r = 0; r < 8; r++)
                    acc[r] += __shfl_xor_sync(0xffffffffu, acc[r], o);
            }
            #pragma unroll
            for (int r = 0; r < 8; r++) {
                float e = mreg[r] * __expf(acc[r] * SCALE);
                if (lane == r) sm->sc[rbase + r] = e;
                zacc += e * pv[r];
            }
            sm->zred[warp][lane] = zacc;
        }
        __syncthreads();

        // ---- publish partials + flag (warp 0; plain stores, no atomics) ----
        if (warp == 0) {
            float s = 0.f;
            #pragma unroll
            for (int w = 0; w < NW; w++) s += sm->zred[w][lane];
            __stcg(&g_part[p][b][lane], s);
            __threadfence();
            if (lane == 0) __stcg(&g_flag[b], t + 2);
        }

        // ---- shadow: a2, deferred attn write, capture this step's e ----
        for (int k = warp; k < VOCAB; k += NW) {
            float acc = 0.f;
            #pragma unroll
            for (int i = 0; i < 16; i++)
                acc += sm->wout_hi[k][lane + 32 * i] * sm->h[lane + 32 * i];
            acc = wsum(acc);
            if (lane == 0) sm->a2[k] = acc + b_out[k];
        }
        if (tid < CHUNK) {
            if (t > 0)
                out[OUT_ATT + (size_t)(t - 1) * T_ENC + j0 + tid] = av * invreg;
            av = sm->sc[tid];
        }

        // ---- wait: 128 threads each poll one block's flag ----
        if (tid < NBW) {
            poll_flag(&g_flag[tid], t + 2);
            __threadfence();
        }
        __syncthreads();

        // ---- prefetch next gh (hides under combine) ----
        float ghr_n = __ldcg(&g_gh[q][tid]);
        float ghz_n = __ldcg(&g_gh[q][HID + tid]);
        float ghn_n = __ldcg(&g_gh[q][2 * HID + tid]);

        // ---- redundant combine (every warp -> tok/inv in regs) ----
        {
            float s = 0.f;
            #pragma unroll
            for (int i = 0; i < 8; i++)
                s += __ldcg(&g_part[p][warp * 8 + i][lane]);
            sm->tot[warp][lane] = s;
        }
        __syncthreads();
        {
            float s = 0.f;
            #pragma unroll
            for (int g = 0; g < NW; g++) s += sm->tot[g][lane];
            float sg  = __shfl_sync(0xffffffffu, s, 31);
            float inv = __fdividef(1.f, sg);
            invreg = inv;
            float lg  = (lane < VOCAB) ? s * inv + sm->a2[lane] : -3.4e38f;
            float bv = lg; int bi = lane;
            #pragma unroll
            for (int o = 16; o; o >>= 1) {
                float ov = __shfl_xor_sync(0xffffffffu, bv, o);
                int   oi = __shfl_xor_sync(0xffffffffu, bi, o);
                if (ov > bv || (ov == bv && oi < bi)) { bv = ov; bi = oi; }
            }
            tok = bi;                       // identical in every warp/block
            if (b == 0 && warp == 0) {
                if (lane < VOCAB) out[(size_t)t * VOCAB + lane] = lg;
                if (lane == 0) {
                    if (bi == EOS && len == STEPS) len = t;
                }
            }
        }
        ghr = ghr_n; ghz = ghz_n; ghn = ghn_n;
    }

    // final attention row + length
    if (tid < CHUNK)
        out[OUT_ATT + (size_t)(STEPS - 1) * T_ENC + j0 + tid] = av * invreg;
    if (b == 0 && warp == 0 && lane == 0) out[OUT_LEN] = (float)len;

    // ================= teardown: one-shot rendezvous, block0 resets ========
    __syncthreads();
    if (tid == 0) {
        __threadfence();
        atomicAdd(&g_arrive, 1);
        if (b == 0) {
            while (*(volatile int*)&g_arrive < NBW) {}
            for (int i = 0; i < NBW; i++) g_flag[i] = 0;
            __threadfence();
            atomicExch(&g_arrive, 0);
        }
    }
}

extern "C" void kernel_launch(void* const* d_in, const int* in_sizes, int n_in,
                              void* d_out, int out_size) {
    const float* enc    = (const float*)d_in[0];
    const float* embed  = (const float*)d_in[2];
    const float* w_ih   = (const float*)d_in[3];
    const float* w_hh   = (const float*)d_in[4];
    const float* b_ih   = (const float*)d_in[5];
    const float* b_hh   = (const float*)d_in[6];
    const float* w_out  = (const float*)d_in[7];
    const float* b_out  = (const float*)d_in[8];
    float* out = (float*)d_out;

    int smem = (int)sizeof(SMW);
    cudaFuncSetAttribute(decoder_kernel,
                         cudaFuncAttributeMaxDynamicSharedMemorySize, smem);
    decoder_kernel<<<NBW, NT, smem>>>(enc, embed, w_ih, w_hh, b_ih, b_hh,
                                      w_out, b_out, out);
}